// round 13
// baseline (speedup 1.0000x reference)
#include <cuda_runtime.h>
#include <cuda_fp16.h>
#include <cstdint>
#include <stdint.h>
#include <math.h>

#define B_   2
#define S_   2048
#define D_   1024
#define H_   16
#define DK_  64
#define DFF_ 4096
#define M_   (B_ * S_)      // 4096 rows
#define EPS_ 1e-6f

// ---------------- scratch (device globals; no allocation allowed) ----------------
__device__ __half g_h  [(size_t)M_ * D_];    // LN output (fp16, reused for LN2)
__device__ __half g_q  [(size_t)M_ * D_];    // (b,h,s,d) fp16, pre-scaled by 0.125
__device__ __half g_k  [(size_t)M_ * D_];    // (b,h,s,d) fp16
__device__ __half g_v  [(size_t)M_ * D_];    // (b,h,s,d) fp16
__device__ __half g_ctx[(size_t)M_ * D_];    // (m, h*DK+d) fp16
__device__ float  g_x2 [(size_t)M_ * D_];    // residual-1 output (exact fp32)
__device__ __half g_ff [(size_t)M_ * DFF_];  // relu(h2@W1+b1), fp16
// transposed fp16 weights: WqT,WkT,WvT (contiguous), WoT, W1T (DFF*D), W2T (D*DFF)
__device__ __half g_wt [(size_t)4 * D_ * D_ + 2 * (size_t)D_ * DFF_];

__device__ __forceinline__ uint32_t fb(float f) { return __float_as_uint(f); }

// ---------------- weight transpose -> fp16: WT[n][k] = (half)W[k][n] -------------
__global__ void transpose_kernel(const float* __restrict__ W, __half* __restrict__ WT,
                                 int K, int N) {
    __shared__ float tile[32][33];
    int k0 = blockIdx.y * 32, n0 = blockIdx.x * 32;
    int tx = threadIdx.x, ty = threadIdx.y;        // (32, 8)
    #pragma unroll
    for (int i = 0; i < 4; i++)
        tile[ty + i * 8][tx] = W[(size_t)(k0 + ty + i * 8) * N + n0 + tx];
    __syncthreads();
    #pragma unroll
    for (int i = 0; i < 4; i++)
        WT[(size_t)(n0 + ty + i * 8) * K + k0 + tx] = __float2half(tile[tx][ty + i * 8]);
}

// -------- layernorm: alpha*(x-mean)/(std+eps)+beta, unbiased std, fp16 output ----
__global__ void layernorm_kernel(const float* __restrict__ x,
                                 const float* __restrict__ alpha,
                                 const float* __restrict__ beta,
                                 __half* __restrict__ out) {
    int row = blockIdx.x;
    int t = threadIdx.x;                       // 256 threads, 4 elems each (D=1024)
    const float4* xr = (const float4*)(x + (size_t)row * D_);
    float4 v = xr[t];
    float s  = v.x + v.y + v.z + v.w;
    float sq = v.x*v.x + v.y*v.y + v.z*v.z + v.w*v.w;
    #pragma unroll
    for (int o = 16; o > 0; o >>= 1) {
        s  += __shfl_xor_sync(0xFFFFFFFFu, s,  o);
        sq += __shfl_xor_sync(0xFFFFFFFFu, sq, o);
    }
    __shared__ float ss[8], sqs[8];
    __shared__ float mean_sh, inv_sh;
    int w = t >> 5;
    if ((t & 31) == 0) { ss[w] = s; sqs[w] = sq; }
    __syncthreads();
    if (t == 0) {
        float S = 0.f, SQ = 0.f;
        #pragma unroll
        for (int i = 0; i < 8; i++) { S += ss[i]; SQ += sqs[i]; }
        float mean = S / (float)D_;
        float var  = (SQ - (float)D_ * mean * mean) / (float)(D_ - 1);
        float sd   = sqrtf(fmaxf(var, 0.f));
        mean_sh = mean;
        inv_sh  = 1.f / (sd + EPS_);
    }
    __syncthreads();
    float a = alpha[0], g = beta[0];
    float mean = mean_sh, inv = inv_sh;
    __half2* o2 = (__half2*)(out + (size_t)row * D_);
    o2[t * 2    ] = __floats2half2_rn(a * (v.x - mean) * inv + g,
                                      a * (v.y - mean) * inv + g);
    o2[t * 2 + 1] = __floats2half2_rn(a * (v.z - mean) * inv + g,
                                      a * (v.w - mean) * inv + g);
}

// ======================= FP16 tensor-core GEMM ===================================
// CTA tile 256x128, 8 warps each 64x64 (A-reads x2, B-reads x4 on double-area tile
// -> smem traffic per FLOP x0.69 vs 128x128). BK=32, 3-stage cp.async pipeline.
#define GTM   256                        // CTA tile M
#define GTN   128                        // CTA tile N
#define FBK   32
#define FSTR  40                         // halves per smem row
#define FATILE (GTM * FSTR)              // 10240 halves
#define FBTILE (GTN * FSTR)              // 5120 halves
#define FSTG  (FATILE + FBTILE)          // per stage
#define F_STAGES 3
#define F_SMEM_BYTES (F_STAGES * FSTG * 2)   // 92160 B

__device__ __forceinline__ void mma_f16(float c[4], const uint32_t a[4],
                                        uint32_t b0, uint32_t b1) {
    asm volatile(
        "mma.sync.aligned.m16n8k16.row.col.f32.f16.f16.f32 "
        "{%0,%1,%2,%3}, {%4,%5,%6,%7}, {%8,%9}, {%0,%1,%2,%3};"
        : "+f"(c[0]), "+f"(c[1]), "+f"(c[2]), "+f"(c[3])
        : "r"(a[0]), "r"(a[1]), "r"(a[2]), "r"(a[3]), "r"(b0), "r"(b1));
}

__device__ __forceinline__ void ldm4(uint32_t r[4], const __half* p) {
    uint32_t a = (uint32_t)__cvta_generic_to_shared(p);
    asm volatile("ldmatrix.sync.aligned.m8n8.x4.shared.b16 {%0,%1,%2,%3}, [%4];"
        : "=r"(r[0]), "=r"(r[1]), "=r"(r[2]), "=r"(r[3]) : "r"(a));
}

__device__ __forceinline__ void ldm4t(uint32_t r[4], const __half* p) {
    uint32_t a = (uint32_t)__cvta_generic_to_shared(p);
    asm volatile("ldmatrix.sync.aligned.m8n8.x4.trans.shared.b16 {%0,%1,%2,%3}, [%4];"
        : "=r"(r[0]), "=r"(r[1]), "=r"(r[2]), "=r"(r[3]) : "r"(a));
}

__device__ __forceinline__ void cp16(void* smem_dst, const void* gsrc) {
    uint32_t s = (uint32_t)__cvta_generic_to_shared(smem_dst);
    asm volatile("cp.async.cg.shared.global [%0], [%1], 16;\n" :: "r"(s), "l"(gsrc));
}

// shared fp16 GEMM mainloop: CTA 256x128, warp 64x64 (wm=warp>>1 in 0..3, wn=warp&1)
__device__ __forceinline__ void gemm_core_f16(const __half* __restrict__ A,
                                              const __half* __restrict__ BT,
                                              __half* sm, int bx, int by, int Kdim,
                                              float acc[4][8][4]) {
    int t = threadIdx.x;
    int lane = t & 31, warp = t >> 5;
    int wm = warp >> 1, wn = warp & 1;
    const int nk = Kdim / FBK;

    int rA = (lane & 7) + ((lane >> 3) & 1) * 8;
    int kA = ((lane >> 4) & 1) * 8;
    int rB = (lane & 7) + ((lane >> 4) & 1) * 8;
    int kB = ((lane >> 3) & 1) * 8;

    auto prefetch = [&](int stage, int k0) {
        __half* ab = sm + stage * FSTG;
        __half* bb = ab + FATILE;
        #pragma unroll
        for (int i = 0; i < 4; i++) {                 // A: 256 rows x 32 halves
            int lin = t + i * 256;                    // 0..1023
            int r = lin >> 2, ch = (lin & 3) * 8;
            cp16(ab + r * FSTR + ch, A + (size_t)(by * GTM + r) * Kdim + k0 + ch);
        }
        #pragma unroll
        for (int i = 0; i < 2; i++) {                 // B: 128 rows x 32 halves
            int lin = t + i * 256;                    // 0..511
            int r = lin >> 2, ch = (lin & 3) * 8;
            cp16(bb + r * FSTR + ch, BT + (size_t)(bx * GTN + r) * Kdim + k0 + ch);
        }
    };

    #pragma unroll
    for (int s = 0; s < F_STAGES; s++) {
        prefetch(s, s * FBK);
        asm volatile("cp.async.commit_group;" ::: "memory");
    }

    for (int kt = 0; kt < nk; kt++) {
        asm volatile("cp.async.wait_group %0;" :: "n"(F_STAGES - 2) : "memory");
        __syncthreads();
        if (kt >= 1) {
            int blk = kt - 1 + F_STAGES;
            if (blk < nk) prefetch((kt - 1) % F_STAGES, blk * FBK);
            asm volatile("cp.async.commit_group;" ::: "memory");
        }

        const __half* pA = sm + (kt % F_STAGES) * FSTG;
        const __half* pB = pA + FATILE;

        #pragma unroll
        for (int kk = 0; kk < 2; kk++) {
            int k16 = kk * 16;
            uint32_t af[4][4];
            #pragma unroll
            for (int mt = 0; mt < 4; mt++)
                ldm4(af[mt], pA + (wm * 64 + mt * 16 + rA) * FSTR + k16 + kA);
            uint32_t bf[4][4];
            #pragma unroll
            for (int p = 0; p < 4; p++)
                ldm4(bf[p], pB + (wn * 64 + p * 16 + rB) * FSTR + k16 + kB);
            #pragma unroll
            for (int mt = 0; mt < 4; mt++)
                #pragma unroll
                for (int nt = 0; nt < 8; nt++)
                    mma_f16(acc[mt][nt], af[mt],
                            bf[nt >> 1][(nt & 1) * 2], bf[nt >> 1][(nt & 1) * 2 + 1]);
        }
    }
}

// EPI 1: bias+relu -> fp16 C.  EPI 2: bias + fp32 residual -> fp32 C.
template<int EPI>
__global__ void __launch_bounds__(256, 1)
gemm_f16(const __half* __restrict__ A,
         const __half* __restrict__ BT,
         const float* __restrict__ bias,
         const float* __restrict__ res,
         void* __restrict__ Cv,
         int Ndim, int Kdim) {
    extern __shared__ __half smh[];
    int bx = blockIdx.x, by = blockIdx.y;
    int lane = threadIdx.x & 31, warp = threadIdx.x >> 5;
    int wm = warp >> 1, wn = warp & 1;
    int gid = lane >> 2, tig = lane & 3;

    float acc[4][8][4];
    #pragma unroll
    for (int mt = 0; mt < 4; mt++)
        #pragma unroll
        for (int nt = 0; nt < 8; nt++)
            #pragma unroll
            for (int c = 0; c < 4; c++) acc[mt][nt][c] = 0.f;

    gemm_core_f16(A, BT, smh, bx, by, Kdim, acc);

    #pragma unroll
    for (int mt = 0; mt < 4; mt++) {
        #pragma unroll
        for (int nt = 0; nt < 8; nt++) {
            #pragma unroll
            for (int half = 0; half < 2; half++) {
                int row = by * GTM + wm * 64 + mt * 16 + gid + half * 8;
                int col = bx * GTN + wn * 64 + nt * 8 + tig * 2;
                float vx = acc[mt][nt][half * 2 + 0] + bias[col];
                float vy = acc[mt][nt][half * 2 + 1] + bias[col + 1];
                if (EPI == 1) {
                    __half2* C = (__half2*)Cv;
                    C[((size_t)row * Ndim + col) >> 1] =
                        __floats2half2_rn(fmaxf(vx, 0.f), fmaxf(vy, 0.f));
                } else {
                    float* C = (float*)Cv;
                    float2 r = *(const float2*)(res + (size_t)row * Ndim + col);
                    *(float2*)(C + (size_t)row * Ndim + col)
                        = make_float2(vx + r.x, vy + r.y);
                }
            }
        }
    }
}

// fused QKV: grid.z in {0,1,2}; fp16 permuted output; Q (z==0) pre-scaled by 0.125
__global__ void __launch_bounds__(256, 1)
gemm_qkv(const __half* __restrict__ A,
         const __half* __restrict__ WTbase,
         const float* __restrict__ bq, const float* __restrict__ bk,
         const float* __restrict__ bv,
         __half* __restrict__ qo, __half* __restrict__ ko, __half* __restrict__ vo) {
    extern __shared__ __half smh[];
    int bx = blockIdx.x, by = blockIdx.y, z = blockIdx.z;
    int lane = threadIdx.x & 31, warp = threadIdx.x >> 5;
    int wm = warp >> 1, wn = warp & 1;
    int gid = lane >> 2, tig = lane & 3;

    const __half* BT  = WTbase + (size_t)z * D_ * D_;
    const float* bias = (z == 0) ? bq : (z == 1) ? bk : bv;
    __half*      C    = (z == 0) ? qo : (z == 1) ? ko : vo;
    float scale = (z == 0) ? 0.125f : 1.0f;

    float acc[4][8][4];
    #pragma unroll
    for (int mt = 0; mt < 4; mt++)
        #pragma unroll
        for (int nt = 0; nt < 8; nt++)
            #pragma unroll
            for (int c = 0; c < 4; c++) acc[mt][nt][c] = 0.f;

    gemm_core_f16(A, BT, smh, bx, by, D_, acc);

    #pragma unroll
    for (int mt = 0; mt < 4; mt++) {
        #pragma unroll
        for (int nt = 0; nt < 8; nt++) {
            #pragma unroll
            for (int half = 0; half < 2; half++) {
                int row = by * GTM + wm * 64 + mt * 16 + gid + half * 8;
                int col = bx * GTN + wn * 64 + nt * 8 + tig * 2;
                float vx = (acc[mt][nt][half * 2 + 0] + bias[col    ]) * scale;
                float vy = (acc[mt][nt][half * 2 + 1] + bias[col + 1]) * scale;
                int bb = row / S_, s = row % S_;
                int hh = col >> 6, dd = col & 63;
                *(__half2*)(C + ((((size_t)bb * H_ + hh) * S_) + s) * DK_ + dd)
                    = __floats2half2_rn(vx, vy);
            }
        }
    }
}

// ================= flash attention, FP16 mma + register softmax ==================
#define FA_STR 72
#define FA_SMEM_BYTES ((128 + 64 + 64 + 128) * FA_STR * 2)   // 55296 B

__global__ void __launch_bounds__(256, 2)
flash_attn_f16(const __half* __restrict__ Q,
               const __half* __restrict__ K,
               const __half* __restrict__ V,
               __half* __restrict__ ctx) {
    extern __shared__ __half smh[];
    __half* smQ = smh;                      // [128][72] q-rows x dims
    __half* smK = smQ + 128 * FA_STR;       // [64][72]  keys x dims
    __half* smV = smK +  64 * FA_STR;       // [64][72]  keys x dims (trans-ld)
    __half* smP = smV +  64 * FA_STR;       // [128][72] q-rows x keys (warp-private)

    int tid = threadIdx.x;
    int lane = tid & 31, wq = tid >> 5;
    int gid = lane >> 2, tig = lane & 3;
    int bh = blockIdx.y, qt = blockIdx.x;
    int qr = wq * 16;

    int rA = (lane & 7) + ((lane >> 3) & 1) * 8;
    int kA = ((lane >> 4) & 1) * 8;
    int rB = (lane & 7) + ((lane >> 4) & 1) * 8;
    int kB = ((lane >> 3) & 1) * 8;
    int rV = (lane & 7) + ((lane >> 3) & 1) * 8;
    int cV = ((lane >> 4) & 1) * 8;

    const __half* Qp = Q + ((size_t)bh * S_ + qt * 128) * DK_;
    const __half* Kp = K + (size_t)bh * S_ * DK_;
    const __half* Vp = V + (size_t)bh * S_ * DK_;

    for (int idx = tid; idx < 128 * 8; idx += 256) {
        int r = idx >> 3, c8 = (idx & 7) * 8;
        *(int4*)(smQ + r * FA_STR + c8) = *(const int4*)(Qp + (size_t)r * DK_ + c8);
    }

    float m0 = -1e30f, m1 = -1e30f, l0 = 0.f, l1 = 0.f;
    float o[8][4];
    #pragma unroll
    for (int nt = 0; nt < 8; nt++)
        #pragma unroll
        for (int c = 0; c < 4; c++) o[nt][c] = 0.f;

    for (int kt = 0; kt < S_ / 64; kt++) {
        __syncthreads();
        const __half* Kt = Kp + (size_t)kt * 64 * DK_;
        const __half* Vt = Vp + (size_t)kt * 64 * DK_;
        for (int idx = tid; idx < 64 * 8; idx += 256) {
            int r = idx >> 3, c8 = (idx & 7) * 8;
            *(int4*)(smK + r * FA_STR + c8) = *(const int4*)(Kt + (size_t)r * DK_ + c8);
            *(int4*)(smV + r * FA_STR + c8) = *(const int4*)(Vt + (size_t)r * DK_ + c8);
        }
        __syncthreads();

        float sacc[8][4];
        #pragma unroll
        for (int nt = 0; nt < 8; nt++)
            #pragma unroll
            for (int c = 0; c < 4; c++) sacc[nt][c] = 0.f;
        #pragma unroll
        for (int kk = 0; kk < 4; kk++) {
            int k16 = kk * 16;
            uint32_t af[4];
            ldm4(af, smQ + (qr + rA) * FA_STR + k16 + kA);
            uint32_t bfm[4][4];
            #pragma unroll
            for (int p = 0; p < 4; p++)
                ldm4(bfm[p], smK + (p * 16 + rB) * FA_STR + k16 + kB);
            #pragma unroll
            for (int nt = 0; nt < 8; nt++)
                mma_f16(sacc[nt], af, bfm[nt >> 1][(nt & 1) * 2],
                                      bfm[nt >> 1][(nt & 1) * 2 + 1]);
        }

        float tmx0 = -1e30f, tmx1 = -1e30f;
        #pragma unroll
        for (int nt = 0; nt < 8; nt++) {
            tmx0 = fmaxf(tmx0, fmaxf(sacc[nt][0], sacc[nt][1]));
            tmx1 = fmaxf(tmx1, fmaxf(sacc[nt][2], sacc[nt][3]));
        }
        tmx0 = fmaxf(tmx0, __shfl_xor_sync(0xFFFFFFFFu, tmx0, 1));
        tmx0 = fmaxf(tmx0, __shfl_xor_sync(0xFFFFFFFFu, tmx0, 2));
        tmx1 = fmaxf(tmx1, __shfl_xor_sync(0xFFFFFFFFu, tmx1, 1));
        tmx1 = fmaxf(tmx1, __shfl_xor_sync(0xFFFFFFFFu, tmx1, 2));
        float nm0 = fmaxf(m0, tmx0), nm1 = fmaxf(m1, tmx1);
        float sum0 = 0.f, sum1 = 0.f;
        #pragma unroll
        for (int nt = 0; nt < 8; nt++) {
            sacc[nt][0] = __expf(sacc[nt][0] - nm0);
            sacc[nt][1] = __expf(sacc[nt][1] - nm0);
            sacc[nt][2] = __expf(sacc[nt][2] - nm1);
            sacc[nt][3] = __expf(sacc[nt][3] - nm1);
            sum0 += sacc[nt][0] + sacc[nt][1];
            sum1 += sacc[nt][2] + sacc[nt][3];
        }
        sum0 += __shfl_xor_sync(0xFFFFFFFFu, sum0, 1);
        sum0 += __shfl_xor_sync(0xFFFFFFFFu, sum0, 2);
        sum1 += __shfl_xor_sync(0xFFFFFFFFu, sum1, 1);
        sum1 += __shfl_xor_sync(0xFFFFFFFFu, sum1, 2);
        float rf0 = __expf(m0 - nm0), rf1 = __expf(m1 - nm1);
        m0 = nm0; m1 = nm1;
        l0 = l0 * rf0 + sum0;
        l1 = l1 * rf1 + sum1;
        #pragma unroll
        for (int nt = 0; nt < 8; nt++) {
            o[nt][0] *= rf0; o[nt][1] *= rf0;
            o[nt][2] *= rf1; o[nt][3] *= rf1;
        }
        #pragma unroll
        for (int nt = 0; nt < 8; nt++) {
            *(__half2*)(smP + (qr + gid    ) * FA_STR + nt * 8 + tig * 2)
                = __floats2half2_rn(sacc[nt][0], sacc[nt][1]);
            *(__half2*)(smP + (qr + gid + 8) * FA_STR + nt * 8 + tig * 2)
                = __floats2half2_rn(sacc[nt][2], sacc[nt][3]);
        }
        __syncwarp();

        #pragma unroll
        for (int kk = 0; kk < 4; kk++) {
            int k16 = kk * 16;
            uint32_t af[4];
            ldm4(af, smP + (qr + rA) * FA_STR + k16 + kA);
            uint32_t bfm[4][4];
            #pragma unroll
            for (int p = 0; p < 4; p++)
                ldm4t(bfm[p], smV + (k16 + rV) * FA_STR + p * 16 + cV);
            #pragma unroll
            for (int nt = 0; nt < 8; nt++)
                mma_f16(o[nt], af, bfm[nt >> 1][(nt & 1) * 2],
                                   bfm[nt >> 1][(nt & 1) * 2 + 1]);
        }
    }

    float inv0 = 1.f / l0, inv1 = 1.f / l1;
    int b = bh >> 4, h = bh & 15;
    int s0 = qt * 128 + qr + gid;
    #pragma unroll
    for (int nt = 0; nt < 8; nt++) {
        int col = h * DK_ + nt * 8 + tig * 2;
        *(__half2*)(ctx + (size_t)(b * S_ + s0    ) * D_ + col)
            = __floats2half2_rn(o[nt][0] * inv0, o[nt][1] * inv0);
        *(__half2*)(ctx + (size_t)(b * S_ + s0 + 8) * D_ + col)
            = __floats2half2_rn(o[nt][2] * inv1, o[nt][3] * inv1);
    }
}

// ---------------- launch ----------------------------------------------------------
extern "C" void kernel_launch(void* const* d_in, const int* in_sizes, int n_in,
                              void* d_out, int out_size) {
    const float* x  = (const float*)d_in[0];
    // d_in[1] = src_mask (no-op in reference, ignored)
    const float* Wq = (const float*)d_in[2];
    const float* bq = (const float*)d_in[3];
    const float* Wk = (const float*)d_in[4];
    const float* bk = (const float*)d_in[5];
    const float* Wv = (const float*)d_in[6];
    const float* bv = (const float*)d_in[7];
    const float* Wo = (const float*)d_in[8];
    const float* bo = (const float*)d_in[9];
    const float* W1 = (const float*)d_in[10];
    const float* b1 = (const float*)d_in[11];
    const float* W2 = (const float*)d_in[12];
    const float* b2 = (const float*)d_in[13];
    const float* a1 = (const float*)d_in[14];
    const float* g1 = (const float*)d_in[15];
    const float* a2 = (const float*)d_in[16];
    const float* g2 = (const float*)d_in[17];
    float* out = (float*)d_out;

    __half *hbuf, *qb, *kb, *vb, *ctx, *ffb, *wt;
    float *x2;
    cudaGetSymbolAddress((void**)&hbuf, g_h);
    cudaGetSymbolAddress((void**)&qb,   g_q);
    cudaGetSymbolAddress((void**)&kb,   g_k);
    cudaGetSymbolAddress((void**)&vb,   g_v);
    cudaGetSymbolAddress((void**)&ctx,  g_ctx);
    cudaGetSymbolAddress((void**)&x2,   g_x2);
    cudaGetSymbolAddress((void**)&ffb,  g_ff);
    cudaGetSymbolAddress((void**)&wt,   g_wt);

    __half* WqT = wt;                                // WqT|WkT|WvT contiguous
    __half* WkT = WqT + (size_t)D_ * D_;
    __half* WvT = WkT + (size_t)D_ * D_;
    __half* WoT = WvT + (size_t)D_ * D_;
    __half* W1T = WoT + (size_t)D_ * D_;             // [DFF][D]
    __half* W2T = W1T + (size_t)D_ * DFF_;           // [D][DFF]

    cudaFuncSetAttribute(flash_attn_f16,
                         cudaFuncAttributeMaxDynamicSharedMemorySize, FA_SMEM_BYTES);
    cudaFuncSetAttribute(gemm_f16<1>, cudaFuncAttributeMaxDynamicSharedMemorySize, F_SMEM_BYTES);
    cudaFuncSetAttribute(gemm_f16<2>, cudaFuncAttributeMaxDynamicSharedMemorySize, F_SMEM_BYTES);
    cudaFuncSetAttribute(gemm_qkv,    cudaFuncAttributeMaxDynamicSharedMemorySize, F_SMEM_BYTES);

    dim3 tb(32, 8);
    // 0. weight transposes -> fp16
    transpose_kernel<<<dim3(D_/32,  D_/32),  tb>>>(Wq, WqT, D_, D_);
    transpose_kernel<<<dim3(D_/32,  D_/32),  tb>>>(Wk, WkT, D_, D_);
    transpose_kernel<<<dim3(D_/32,  D_/32),  tb>>>(Wv, WvT, D_, D_);
    transpose_kernel<<<dim3(D_/32,  D_/32),  tb>>>(Wo, WoT, D_, D_);
    transpose_kernel<<<dim3(DFF_/32, D_/32), tb>>>(W1, W1T, D_, DFF_);
    transpose_kernel<<<dim3(D_/32, DFF_/32), tb>>>(W2, W2T, DFF_, D_);

    dim3 gD(D_ / GTN, M_ / GTM);        // (8, 16)
    dim3 gQKV(D_ / GTN, M_ / GTM, 3);   // fused QKV
    dim3 gF(DFF_ / GTN, M_ / GTM);      // (32, 16)

    // 1. LN1 -> fp16
    layernorm_kernel<<<M_, 256>>>(x, a1, g1, hbuf);
    // 2. QKV projections (fp16 gemm, fp16 permuted store, Q pre-scaled)
    gemm_qkv<<<gQKV, 256, F_SMEM_BYTES>>>(hbuf, WqT, bq, bk, bv, qb, kb, vb);
    // 3. attention (fp16 tensor-core)
    flash_attn_f16<<<dim3(S_ / 128, B_ * H_), 256, FA_SMEM_BYTES>>>(qb, kb, vb, ctx);
    // 4. O projection + residual 1 (fp32 exact residual)
    gemm_f16<2><<<gD, 256, F_SMEM_BYTES>>>(ctx, WoT, bo, x, x2, D_, D_);
    // 5. LN2 -> fp16
    layernorm_kernel<<<M_, 256>>>(x2, a2, g2, hbuf);
    // 6. FFN up + ReLU -> fp16
    gemm_f16<1><<<gF, 256, F_SMEM_BYTES>>>(hbuf, W1T, b1, nullptr, ffb, DFF_, D_);
    // 7. FFN down + residual 2 -> output (fp32)
    gemm_f16<2><<<gD, 256, F_SMEM_BYTES>>>(ffb, W2T, b2, x2, out, D_, DFF_);
}

// round 14
// speedup vs baseline: 1.1261x; 1.1261x over previous
#include <cuda_runtime.h>
#include <cuda_fp16.h>
#include <cstdint>
#include <stdint.h>
#include <math.h>

#define B_   2
#define S_   2048
#define D_   1024
#define H_   16
#define DK_  64
#define DFF_ 4096
#define M_   (B_ * S_)      // 4096 rows
#define EPS_ 1e-6f

// ---------------- scratch (device globals; no allocation allowed) ----------------
__device__ __half g_h  [(size_t)M_ * D_];    // LN output (fp16, reused for LN2)
__device__ __half g_q  [(size_t)M_ * D_];    // (b,h,s,d) fp16, pre-scaled by 0.125
__device__ __half g_k  [(size_t)M_ * D_];    // (b,h,s,d) fp16
__device__ __half g_v  [(size_t)M_ * D_];    // (b,h,s,d) fp16
__device__ __half g_ctx[(size_t)M_ * D_];    // (m, h*DK+d) fp16
__device__ float  g_x2 [(size_t)M_ * D_];    // residual-1 output (exact fp32)
__device__ __half g_ff [(size_t)M_ * DFF_];  // relu(h2@W1+b1), fp16
// transposed fp16 weights: WqT,WkT,WvT (contiguous), WoT, W1T (DFF*D), W2T (D*DFF)
__device__ __half g_wt [(size_t)4 * D_ * D_ + 2 * (size_t)D_ * DFF_];

__device__ __forceinline__ uint32_t fb(float f) { return __float_as_uint(f); }

// ------- fused weight transposes -> fp16: one launch, flattened block ranges -----
// blocks: [0,1024) Wq, [1024,2048) Wk, [2048,3072) Wv, [3072,4096) Wo,
//         [4096,8192) W1 (K=1024,N=4096), [8192,12288) W2 (K=4096,N=1024)
__global__ void transpose_all(const float* __restrict__ Wq, const float* __restrict__ Wk,
                              const float* __restrict__ Wv, const float* __restrict__ Wo,
                              const float* __restrict__ W1, const float* __restrict__ W2,
                              __half* __restrict__ WqT, __half* __restrict__ WkT,
                              __half* __restrict__ WvT, __half* __restrict__ WoT,
                              __half* __restrict__ W1T, __half* __restrict__ W2T) {
    int bid = blockIdx.x;
    const float* W; __half* WT; int K, N, local;
    if      (bid <  1024) { W = Wq; WT = WqT; K = D_;   N = D_;   local = bid; }
    else if (bid <  2048) { W = Wk; WT = WkT; K = D_;   N = D_;   local = bid - 1024; }
    else if (bid <  3072) { W = Wv; WT = WvT; K = D_;   N = D_;   local = bid - 2048; }
    else if (bid <  4096) { W = Wo; WT = WoT; K = D_;   N = D_;   local = bid - 3072; }
    else if (bid <  8192) { W = W1; WT = W1T; K = D_;   N = DFF_; local = bid - 4096; }
    else                  { W = W2; WT = W2T; K = DFF_; N = D_;   local = bid - 8192; }
    int nbx = N / 32;
    int by = local / nbx, bx = local % nbx;

    __shared__ float tile[32][33];
    int k0 = by * 32, n0 = bx * 32;
    int tx = threadIdx.x, ty = threadIdx.y;        // (32, 8)
    #pragma unroll
    for (int i = 0; i < 4; i++)
        tile[ty + i * 8][tx] = W[(size_t)(k0 + ty + i * 8) * N + n0 + tx];
    __syncthreads();
    #pragma unroll
    for (int i = 0; i < 4; i++)
        WT[(size_t)(n0 + ty + i * 8) * K + k0 + tx] = __float2half(tile[tx][ty + i * 8]);
}

// -------- layernorm: alpha*(x-mean)/(std+eps)+beta, unbiased std, fp16 output ----
__global__ void layernorm_kernel(const float* __restrict__ x,
                                 const float* __restrict__ alpha,
                                 const float* __restrict__ beta,
                                 __half* __restrict__ out) {
    int row = blockIdx.x;
    int t = threadIdx.x;                       // 256 threads, 4 elems each (D=1024)
    const float4* xr = (const float4*)(x + (size_t)row * D_);
    float4 v = xr[t];
    float s  = v.x + v.y + v.z + v.w;
    float sq = v.x*v.x + v.y*v.y + v.z*v.z + v.w*v.w;
    #pragma unroll
    for (int o = 16; o > 0; o >>= 1) {
        s  += __shfl_xor_sync(0xFFFFFFFFu, s,  o);
        sq += __shfl_xor_sync(0xFFFFFFFFu, sq, o);
    }
    __shared__ float ss[8], sqs[8];
    __shared__ float mean_sh, inv_sh;
    int w = t >> 5;
    if ((t & 31) == 0) { ss[w] = s; sqs[w] = sq; }
    __syncthreads();
    if (t == 0) {
        float S = 0.f, SQ = 0.f;
        #pragma unroll
        for (int i = 0; i < 8; i++) { S += ss[i]; SQ += sqs[i]; }
        float mean = S / (float)D_;
        float var  = (SQ - (float)D_ * mean * mean) / (float)(D_ - 1);
        float sd   = sqrtf(fmaxf(var, 0.f));
        mean_sh = mean;
        inv_sh  = 1.f / (sd + EPS_);
    }
    __syncthreads();
    float a = alpha[0], g = beta[0];
    float mean = mean_sh, inv = inv_sh;
    __half2* o2 = (__half2*)(out + (size_t)row * D_);
    o2[t * 2    ] = __floats2half2_rn(a * (v.x - mean) * inv + g,
                                      a * (v.y - mean) * inv + g);
    o2[t * 2 + 1] = __floats2half2_rn(a * (v.z - mean) * inv + g,
                                      a * (v.w - mean) * inv + g);
}

// ======================= FP16 tensor-core GEMM ===================================
// CTA tile 128x128, 8 warps each 32x64. BK=32, 4-stage cp.async pipeline.
#define FBK   32
#define FSTR  40                         // halves per smem row
#define FTILE (128 * FSTR)               // 5120 halves per tile
#define FSTG  (2 * FTILE)                // A + BT per stage (halves)
#define F_STAGES 4
#define F_SMEM_BYTES (F_STAGES * FSTG * 2)   // 81920 B

__device__ __forceinline__ void mma_f16(float c[4], const uint32_t a[4],
                                        uint32_t b0, uint32_t b1) {
    asm volatile(
        "mma.sync.aligned.m16n8k16.row.col.f32.f16.f16.f32 "
        "{%0,%1,%2,%3}, {%4,%5,%6,%7}, {%8,%9}, {%0,%1,%2,%3};"
        : "+f"(c[0]), "+f"(c[1]), "+f"(c[2]), "+f"(c[3])
        : "r"(a[0]), "r"(a[1]), "r"(a[2]), "r"(a[3]), "r"(b0), "r"(b1));
}

__device__ __forceinline__ void ldm4(uint32_t r[4], const __half* p) {
    uint32_t a = (uint32_t)__cvta_generic_to_shared(p);
    asm volatile("ldmatrix.sync.aligned.m8n8.x4.shared.b16 {%0,%1,%2,%3}, [%4];"
        : "=r"(r[0]), "=r"(r[1]), "=r"(r[2]), "=r"(r[3]) : "r"(a));
}

__device__ __forceinline__ void ldm4t(uint32_t r[4], const __half* p) {
    uint32_t a = (uint32_t)__cvta_generic_to_shared(p);
    asm volatile("ldmatrix.sync.aligned.m8n8.x4.trans.shared.b16 {%0,%1,%2,%3}, [%4];"
        : "=r"(r[0]), "=r"(r[1]), "=r"(r[2]), "=r"(r[3]) : "r"(a));
}

__device__ __forceinline__ void cp16(void* smem_dst, const void* gsrc) {
    uint32_t s = (uint32_t)__cvta_generic_to_shared(smem_dst);
    asm volatile("cp.async.cg.shared.global [%0], [%1], 16;\n" :: "r"(s), "l"(gsrc));
}

// shared fp16 GEMM mainloop
__device__ __forceinline__ void gemm_core_f16(const __half* __restrict__ A,
                                              const __half* __restrict__ BT,
                                              __half* sm, int bx, int by, int Kdim,
                                              float acc[2][8][4]) {
    int t = threadIdx.x;
    int lane = t & 31, warp = t >> 5;
    int wm = warp >> 1, wn = warp & 1;
    const int nk = Kdim / FBK;

    int rA = (lane & 7) + ((lane >> 3) & 1) * 8;
    int kA = ((lane >> 4) & 1) * 8;
    int rB = (lane & 7) + ((lane >> 4) & 1) * 8;
    int kB = ((lane >> 3) & 1) * 8;

    auto prefetch = [&](int stage, int k0) {
        __half* ab = sm + stage * FSTG;
        __half* bb = ab + FTILE;
        #pragma unroll
        for (int i = 0; i < 2; i++) {
            int lin = t + i * 256;
            int r = lin >> 2, ch = (lin & 3) * 8;
            cp16(ab + r * FSTR + ch, A  + (size_t)(by * 128 + r) * Kdim + k0 + ch);
            cp16(bb + r * FSTR + ch, BT + (size_t)(bx * 128 + r) * Kdim + k0 + ch);
        }
    };

    #pragma unroll
    for (int s = 0; s < F_STAGES; s++) {
        prefetch(s, s * FBK);
        asm volatile("cp.async.commit_group;" ::: "memory");
    }

    for (int kt = 0; kt < nk; kt++) {
        asm volatile("cp.async.wait_group %0;" :: "n"(F_STAGES - 2) : "memory");
        __syncthreads();
        if (kt >= 1) {
            int blk = kt - 1 + F_STAGES;
            if (blk < nk) prefetch((kt - 1) % F_STAGES, blk * FBK);
            asm volatile("cp.async.commit_group;" ::: "memory");
        }

        const __half* pA = sm + (kt % F_STAGES) * FSTG;
        const __half* pB = pA + FTILE;

        #pragma unroll
        for (int kk = 0; kk < 2; kk++) {
            int k16 = kk * 16;
            uint32_t af[2][4];
            #pragma unroll
            for (int mt = 0; mt < 2; mt++)
                ldm4(af[mt], pA + (wm * 32 + mt * 16 + rA) * FSTR + k16 + kA);
            uint32_t bf[4][4];
            #pragma unroll
            for (int p = 0; p < 4; p++)
                ldm4(bf[p], pB + (wn * 64 + p * 16 + rB) * FSTR + k16 + kB);
            #pragma unroll
            for (int nt = 0; nt < 8; nt++) {
                uint32_t b0 = bf[nt >> 1][(nt & 1) * 2];
                uint32_t b1 = bf[nt >> 1][(nt & 1) * 2 + 1];
                mma_f16(acc[0][nt], af[0], b0, b1);
                mma_f16(acc[1][nt], af[1], b0, b1);
            }
        }
    }
}

// EPI 1: bias+relu -> fp16 C.  EPI 2: bias + fp32 residual -> fp32 C.
template<int EPI>
__global__ void __launch_bounds__(256, 2)
gemm_f16(const __half* __restrict__ A,
         const __half* __restrict__ BT,
         const float* __restrict__ bias,
         const float* __restrict__ res,
         void* __restrict__ Cv,
         int Ndim, int Kdim) {
    extern __shared__ __half smh[];
    int bx = blockIdx.x, by = blockIdx.y;
    int lane = threadIdx.x & 31, warp = threadIdx.x >> 5;
    int wm = warp >> 1, wn = warp & 1;
    int gid = lane >> 2, tig = lane & 3;

    float acc[2][8][4];
    #pragma unroll
    for (int mt = 0; mt < 2; mt++)
        #pragma unroll
        for (int nt = 0; nt < 8; nt++)
            #pragma unroll
            for (int c = 0; c < 4; c++) acc[mt][nt][c] = 0.f;

    gemm_core_f16(A, BT, smh, bx, by, Kdim, acc);

    #pragma unroll
    for (int mt = 0; mt < 2; mt++) {
        #pragma unroll
        for (int nt = 0; nt < 8; nt++) {
            #pragma unroll
            for (int half = 0; half < 2; half++) {
                int row = by * 128 + wm * 32 + mt * 16 + gid + half * 8;
                int col = bx * 128 + wn * 64 + nt * 8 + tig * 2;
                float vx = acc[mt][nt][half * 2 + 0] + bias[col];
                float vy = acc[mt][nt][half * 2 + 1] + bias[col + 1];
                if (EPI == 1) {
                    __half2* C = (__half2*)Cv;
                    C[((size_t)row * Ndim + col) >> 1] =
                        __floats2half2_rn(fmaxf(vx, 0.f), fmaxf(vy, 0.f));
                } else {
                    float* C = (float*)Cv;
                    float2 r = *(const float2*)(res + (size_t)row * Ndim + col);
                    *(float2*)(C + (size_t)row * Ndim + col)
                        = make_float2(vx + r.x, vy + r.y);
                }
            }
        }
    }
}

// fused QKV: grid.z in {0,1,2}; fp16 permuted output; Q (z==0) pre-scaled by 0.125
__global__ void __launch_bounds__(256, 2)
gemm_qkv(const __half* __restrict__ A,
         const __half* __restrict__ WTbase,
         const float* __restrict__ bq, const float* __restrict__ bk,
         const float* __restrict__ bv,
         __half* __restrict__ qo, __half* __restrict__ ko, __half* __restrict__ vo) {
    extern __shared__ __half smh[];
    int bx = blockIdx.x, by = blockIdx.y, z = blockIdx.z;
    int lane = threadIdx.x & 31, warp = threadIdx.x >> 5;
    int wm = warp >> 1, wn = warp & 1;
    int gid = lane >> 2, tig = lane & 3;

    const __half* BT  = WTbase + (size_t)z * D_ * D_;
    const float* bias = (z == 0) ? bq : (z == 1) ? bk : bv;
    __half*      C    = (z == 0) ? qo : (z == 1) ? ko : vo;
    float scale = (z == 0) ? 0.125f : 1.0f;

    float acc[2][8][4];
    #pragma unroll
    for (int mt = 0; mt < 2; mt++)
        #pragma unroll
        for (int nt = 0; nt < 8; nt++)
            #pragma unroll
            for (int c = 0; c < 4; c++) acc[mt][nt][c] = 0.f;

    gemm_core_f16(A, BT, smh, bx, by, D_, acc);

    #pragma unroll
    for (int mt = 0; mt < 2; mt++) {
        #pragma unroll
        for (int nt = 0; nt < 8; nt++) {
            #pragma unroll
            for (int half = 0; half < 2; half++) {
                int row = by * 128 + wm * 32 + mt * 16 + gid + half * 8;
                int col = bx * 128 + wn * 64 + nt * 8 + tig * 2;
                float vx = (acc[mt][nt][half * 2 + 0] + bias[col    ]) * scale;
                float vy = (acc[mt][nt][half * 2 + 1] + bias[col + 1]) * scale;
                int bb = row / S_, s = row % S_;
                int hh = col >> 6, dd = col & 63;
                *(__half2*)(C + ((((size_t)bb * H_ + hh) * S_) + s) * DK_ + dd)
                    = __floats2half2_rn(vx, vy);
            }
        }
    }
}

// ================= flash attention, FP16 mma + register softmax ==================
#define FA_STR 72
#define FA_SMEM_BYTES ((128 + 64 + 64 + 128) * FA_STR * 2)   // 55296 B

__global__ void __launch_bounds__(256, 2)
flash_attn_f16(const __half* __restrict__ Q,
               const __half* __restrict__ K,
               const __half* __restrict__ V,
               __half* __restrict__ ctx) {
    extern __shared__ __half smh[];
    __half* smQ = smh;                      // [128][72] q-rows x dims
    __half* smK = smQ + 128 * FA_STR;       // [64][72]  keys x dims
    __half* smV = smK +  64 * FA_STR;       // [64][72]  keys x dims (trans-ld)
    __half* smP = smV +  64 * FA_STR;       // [128][72] q-rows x keys (warp-private)

    int tid = threadIdx.x;
    int lane = tid & 31, wq = tid >> 5;
    int gid = lane >> 2, tig = lane & 3;
    int bh = blockIdx.y, qt = blockIdx.x;
    int qr = wq * 16;

    int rA = (lane & 7) + ((lane >> 3) & 1) * 8;
    int kA = ((lane >> 4) & 1) * 8;
    int rB = (lane & 7) + ((lane >> 4) & 1) * 8;
    int kB = ((lane >> 3) & 1) * 8;
    int rV = (lane & 7) + ((lane >> 3) & 1) * 8;
    int cV = ((lane >> 4) & 1) * 8;

    const __half* Qp = Q + ((size_t)bh * S_ + qt * 128) * DK_;
    const __half* Kp = K + (size_t)bh * S_ * DK_;
    const __half* Vp = V + (size_t)bh * S_ * DK_;

    for (int idx = tid; idx < 128 * 8; idx += 256) {
        int r = idx >> 3, c8 = (idx & 7) * 8;
        *(int4*)(smQ + r * FA_STR + c8) = *(const int4*)(Qp + (size_t)r * DK_ + c8);
    }

    float m0 = -1e30f, m1 = -1e30f, l0 = 0.f, l1 = 0.f;
    float o[8][4];
    #pragma unroll
    for (int nt = 0; nt < 8; nt++)
        #pragma unroll
        for (int c = 0; c < 4; c++) o[nt][c] = 0.f;

    for (int kt = 0; kt < S_ / 64; kt++) {
        __syncthreads();
        const __half* Kt = Kp + (size_t)kt * 64 * DK_;
        const __half* Vt = Vp + (size_t)kt * 64 * DK_;
        for (int idx = tid; idx < 64 * 8; idx += 256) {
            int r = idx >> 3, c8 = (idx & 7) * 8;
            *(int4*)(smK + r * FA_STR + c8) = *(const int4*)(Kt + (size_t)r * DK_ + c8);
            *(int4*)(smV + r * FA_STR + c8) = *(const int4*)(Vt + (size_t)r * DK_ + c8);
        }
        __syncthreads();

        float sacc[8][4];
        #pragma unroll
        for (int nt = 0; nt < 8; nt++)
            #pragma unroll
            for (int c = 0; c < 4; c++) sacc[nt][c] = 0.f;
        #pragma unroll
        for (int kk = 0; kk < 4; kk++) {
            int k16 = kk * 16;
            uint32_t af[4];
            ldm4(af, smQ + (qr + rA) * FA_STR + k16 + kA);
            uint32_t bfm[4][4];
            #pragma unroll
            for (int p = 0; p < 4; p++)
                ldm4(bfm[p], smK + (p * 16 + rB) * FA_STR + k16 + kB);
            #pragma unroll
            for (int nt = 0; nt < 8; nt++)
                mma_f16(sacc[nt], af, bfm[nt >> 1][(nt & 1) * 2],
                                      bfm[nt >> 1][(nt & 1) * 2 + 1]);
        }

        float tmx0 = -1e30f, tmx1 = -1e30f;
        #pragma unroll
        for (int nt = 0; nt < 8; nt++) {
            tmx0 = fmaxf(tmx0, fmaxf(sacc[nt][0], sacc[nt][1]));
            tmx1 = fmaxf(tmx1, fmaxf(sacc[nt][2], sacc[nt][3]));
        }
        tmx0 = fmaxf(tmx0, __shfl_xor_sync(0xFFFFFFFFu, tmx0, 1));
        tmx0 = fmaxf(tmx0, __shfl_xor_sync(0xFFFFFFFFu, tmx0, 2));
        tmx1 = fmaxf(tmx1, __shfl_xor_sync(0xFFFFFFFFu, tmx1, 1));
        tmx1 = fmaxf(tmx1, __shfl_xor_sync(0xFFFFFFFFu, tmx1, 2));
        float nm0 = fmaxf(m0, tmx0), nm1 = fmaxf(m1, tmx1);
        float sum0 = 0.f, sum1 = 0.f;
        #pragma unroll
        for (int nt = 0; nt < 8; nt++) {
            sacc[nt][0] = __expf(sacc[nt][0] - nm0);
            sacc[nt][1] = __expf(sacc[nt][1] - nm0);
            sacc[nt][2] = __expf(sacc[nt][2] - nm1);
            sacc[nt][3] = __expf(sacc[nt][3] - nm1);
            sum0 += sacc[nt][0] + sacc[nt][1];
            sum1 += sacc[nt][2] + sacc[nt][3];
        }
        sum0 += __shfl_xor_sync(0xFFFFFFFFu, sum0, 1);
        sum0 += __shfl_xor_sync(0xFFFFFFFFu, sum0, 2);
        sum1 += __shfl_xor_sync(0xFFFFFFFFu, sum1, 1);
        sum1 += __shfl_xor_sync(0xFFFFFFFFu, sum1, 2);
        float rf0 = __expf(m0 - nm0), rf1 = __expf(m1 - nm1);
        m0 = nm0; m1 = nm1;
        l0 = l0 * rf0 + sum0;
        l1 = l1 * rf1 + sum1;
        #pragma unroll
        for (int nt = 0; nt < 8; nt++) {
            o[nt][0] *= rf0; o[nt][1] *= rf0;
            o[nt][2] *= rf1; o[nt][3] *= rf1;
        }
        #pragma unroll
        for (int nt = 0; nt < 8; nt++) {
            *(__half2*)(smP + (qr + gid    ) * FA_STR + nt * 8 + tig * 2)
                = __floats2half2_rn(sacc[nt][0], sacc[nt][1]);
            *(__half2*)(smP + (qr + gid + 8) * FA_STR + nt * 8 + tig * 2)
                = __floats2half2_rn(sacc[nt][2], sacc[nt][3]);
        }
        __syncwarp();

        #pragma unroll
        for (int kk = 0; kk < 4; kk++) {
            int k16 = kk * 16;
            uint32_t af[4];
            ldm4(af, smP + (qr + rA) * FA_STR + k16 + kA);
            uint32_t bfm[4][4];
            #pragma unroll
            for (int p = 0; p < 4; p++)
                ldm4t(bfm[p], smV + (k16 + rV) * FA_STR + p * 16 + cV);
            #pragma unroll
            for (int nt = 0; nt < 8; nt++)
                mma_f16(o[nt], af, bfm[nt >> 1][(nt & 1) * 2],
                                   bfm[nt >> 1][(nt & 1) * 2 + 1]);
        }
    }

    float inv0 = 1.f / l0, inv1 = 1.f / l1;
    int b = bh >> 4, h = bh & 15;
    int s0 = qt * 128 + qr + gid;
    #pragma unroll
    for (int nt = 0; nt < 8; nt++) {
        int col = h * DK_ + nt * 8 + tig * 2;
        *(__half2*)(ctx + (size_t)(b * S_ + s0    ) * D_ + col)
            = __floats2half2_rn(o[nt][0] * inv0, o[nt][1] * inv0);
        *(__half2*)(ctx + (size_t)(b * S_ + s0 + 8) * D_ + col)
            = __floats2half2_rn(o[nt][2] * inv1, o[nt][3] * inv1);
    }
}

// ---------------- launch ----------------------------------------------------------
extern "C" void kernel_launch(void* const* d_in, const int* in_sizes, int n_in,
                              void* d_out, int out_size) {
    const float* x  = (const float*)d_in[0];
    // d_in[1] = src_mask (no-op in reference, ignored)
    const float* Wq = (const float*)d_in[2];
    const float* bq = (const float*)d_in[3];
    const float* Wk = (const float*)d_in[4];
    const float* bk = (const float*)d_in[5];
    const float* Wv = (const float*)d_in[6];
    const float* bv = (const float*)d_in[7];
    const float* Wo = (const float*)d_in[8];
    const float* bo = (const float*)d_in[9];
    const float* W1 = (const float*)d_in[10];
    const float* b1 = (const float*)d_in[11];
    const float* W2 = (const float*)d_in[12];
    const float* b2 = (const float*)d_in[13];
    const float* a1 = (const float*)d_in[14];
    const float* g1 = (const float*)d_in[15];
    const float* a2 = (const float*)d_in[16];
    const float* g2 = (const float*)d_in[17];
    float* out = (float*)d_out;

    __half *hbuf, *qb, *kb, *vb, *ctx, *ffb, *wt;
    float *x2;
    cudaGetSymbolAddress((void**)&hbuf, g_h);
    cudaGetSymbolAddress((void**)&qb,   g_q);
    cudaGetSymbolAddress((void**)&kb,   g_k);
    cudaGetSymbolAddress((void**)&vb,   g_v);
    cudaGetSymbolAddress((void**)&ctx,  g_ctx);
    cudaGetSymbolAddress((void**)&x2,   g_x2);
    cudaGetSymbolAddress((void**)&ffb,  g_ff);
    cudaGetSymbolAddress((void**)&wt,   g_wt);

    __half* WqT = wt;                                // WqT|WkT|WvT contiguous
    __half* WkT = WqT + (size_t)D_ * D_;
    __half* WvT = WkT + (size_t)D_ * D_;
    __half* WoT = WvT + (size_t)D_ * D_;
    __half* W1T = WoT + (size_t)D_ * D_;             // [DFF][D]
    __half* W2T = W1T + (size_t)D_ * DFF_;           // [D][DFF]

    cudaFuncSetAttribute(flash_attn_f16,
                         cudaFuncAttributeMaxDynamicSharedMemorySize, FA_SMEM_BYTES);
    cudaFuncSetAttribute(gemm_f16<1>, cudaFuncAttributeMaxDynamicSharedMemorySize, F_SMEM_BYTES);
    cudaFuncSetAttribute(gemm_f16<2>, cudaFuncAttributeMaxDynamicSharedMemorySize, F_SMEM_BYTES);
    cudaFuncSetAttribute(gemm_qkv,    cudaFuncAttributeMaxDynamicSharedMemorySize, F_SMEM_BYTES);

    // 0. all weight transposes -> fp16, single launch
    transpose_all<<<12288, dim3(32, 8)>>>(Wq, Wk, Wv, Wo, W1, W2,
                                          WqT, WkT, WvT, WoT, W1T, W2T);

    dim3 gD(D_ / 128, M_ / 128);        // (8, 32)
    dim3 gQKV(D_ / 128, M_ / 128, 3);   // fused QKV
    dim3 gF(DFF_ / 128, M_ / 128);      // (32, 32)

    // 1. LN1 -> fp16
    layernorm_kernel<<<M_, 256>>>(x, a1, g1, hbuf);
    // 2. QKV projections (fp16 gemm, fp16 permuted store, Q pre-scaled)
    gemm_qkv<<<gQKV, 256, F_SMEM_BYTES>>>(hbuf, WqT, bq, bk, bv, qb, kb, vb);
    // 3. attention (fp16 tensor-core)
    flash_attn_f16<<<dim3(S_ / 128, B_ * H_), 256, FA_SMEM_BYTES>>>(qb, kb, vb, ctx);
    // 4. O projection + residual 1 (fp32 exact residual)
    gemm_f16<2><<<gD, 256, F_SMEM_BYTES>>>(ctx, WoT, bo, x, x2, D_, D_);
    // 5. LN2 -> fp16
    layernorm_kernel<<<M_, 256>>>(x2, a2, g2, hbuf);
    // 6. FFN up + ReLU -> fp16
    gemm_f16<1><<<gF, 256, F_SMEM_BYTES>>>(hbuf, W1T, b1, nullptr, ffb, DFF_, D_);
    // 7. FFN down + residual 2 -> output (fp32)
    gemm_f16<2><<<gD, 256, F_SMEM_BYTES>>>(ffb, W2T, b2, x2, out, D_, DFF_);
}

// round 15
// speedup vs baseline: 1.1961x; 1.0622x over previous
#include <cuda_runtime.h>
#include <cuda_fp16.h>
#include <cstdint>
#include <stdint.h>
#include <math.h>

#define B_   2
#define S_   2048
#define D_   1024
#define H_   16
#define DK_  64
#define DFF_ 4096
#define M_   (B_ * S_)      // 4096 rows
#define EPS_ 1e-6f

// ---------------- scratch (device globals; no allocation allowed) ----------------
__device__ __half g_h  [(size_t)M_ * D_];    // LN output (fp16, reused for LN2)
__device__ __half g_q  [(size_t)M_ * D_];    // (b,h,s,d) fp16, pre-scaled by 0.125
__device__ __half g_k  [(size_t)M_ * D_];    // (b,h,s,d) fp16
__device__ __half g_v  [(size_t)M_ * D_];    // (b,h,s,d) fp16
__device__ __half g_ctx[(size_t)M_ * D_];    // (m, h*DK+d) fp16
__device__ float  g_x2 [(size_t)M_ * D_];    // residual-1 output (exact fp32)
__device__ __half g_ff [(size_t)M_ * DFF_];  // relu(h2@W1+b1), fp16
// transposed fp16 weights: WqT,WkT,WvT (contiguous), WoT, W1T (DFF*D), W2T (D*DFF)
__device__ __half g_wt [(size_t)4 * D_ * D_ + 2 * (size_t)D_ * DFF_];

__device__ __forceinline__ uint32_t fb(float f) { return __float_as_uint(f); }
__device__ __forceinline__ uint32_t packh2(float lo, float hi) {
    __half2 h = __floats2half2_rn(lo, hi);
    return *(uint32_t*)&h;
}

// ------- fused weight transposes -> fp16: one launch, flattened block ranges -----
__global__ void transpose_all(const float* __restrict__ Wq, const float* __restrict__ Wk,
                              const float* __restrict__ Wv, const float* __restrict__ Wo,
                              const float* __restrict__ W1, const float* __restrict__ W2,
                              __half* __restrict__ WqT, __half* __restrict__ WkT,
                              __half* __restrict__ WvT, __half* __restrict__ WoT,
                              __half* __restrict__ W1T, __half* __restrict__ W2T) {
    int bid = blockIdx.x;
    const float* W; __half* WT; int K, N, local;
    if      (bid <  1024) { W = Wq; WT = WqT; K = D_;   N = D_;   local = bid; }
    else if (bid <  2048) { W = Wk; WT = WkT; K = D_;   N = D_;   local = bid - 1024; }
    else if (bid <  3072) { W = Wv; WT = WvT; K = D_;   N = D_;   local = bid - 2048; }
    else if (bid <  4096) { W = Wo; WT = WoT; K = D_;   N = D_;   local = bid - 3072; }
    else if (bid <  8192) { W = W1; WT = W1T; K = D_;   N = DFF_; local = bid - 4096; }
    else                  { W = W2; WT = W2T; K = DFF_; N = D_;   local = bid - 8192; }
    int nbx = N / 32;
    int by = local / nbx, bx = local % nbx;

    __shared__ float tile[32][33];
    int k0 = by * 32, n0 = bx * 32;
    int tx = threadIdx.x, ty = threadIdx.y;        // (32, 8)
    #pragma unroll
    for (int i = 0; i < 4; i++)
        tile[ty + i * 8][tx] = W[(size_t)(k0 + ty + i * 8) * N + n0 + tx];
    __syncthreads();
    #pragma unroll
    for (int i = 0; i < 4; i++)
        WT[(size_t)(n0 + ty + i * 8) * K + k0 + tx] = __float2half(tile[tx][ty + i * 8]);
}

// -------- layernorm: alpha*(x-mean)/(std+eps)+beta, unbiased std, fp16 output ----
__global__ void layernorm_kernel(const float* __restrict__ x,
                                 const float* __restrict__ alpha,
                                 const float* __restrict__ beta,
                                 __half* __restrict__ out) {
    int row = blockIdx.x;
    int t = threadIdx.x;                       // 256 threads, 4 elems each (D=1024)
    const float4* xr = (const float4*)(x + (size_t)row * D_);
    float4 v = xr[t];
    float s  = v.x + v.y + v.z + v.w;
    float sq = v.x*v.x + v.y*v.y + v.z*v.z + v.w*v.w;
    #pragma unroll
    for (int o = 16; o > 0; o >>= 1) {
        s  += __shfl_xor_sync(0xFFFFFFFFu, s,  o);
        sq += __shfl_xor_sync(0xFFFFFFFFu, sq, o);
    }
    __shared__ float ss[8], sqs[8];
    __shared__ float mean_sh, inv_sh;
    int w = t >> 5;
    if ((t & 31) == 0) { ss[w] = s; sqs[w] = sq; }
    __syncthreads();
    if (t == 0) {
        float S = 0.f, SQ = 0.f;
        #pragma unroll
        for (int i = 0; i < 8; i++) { S += ss[i]; SQ += sqs[i]; }
        float mean = S / (float)D_;
        float var  = (SQ - (float)D_ * mean * mean) / (float)(D_ - 1);
        float sd   = sqrtf(fmaxf(var, 0.f));
        mean_sh = mean;
        inv_sh  = 1.f / (sd + EPS_);
    }
    __syncthreads();
    float a = alpha[0], g = beta[0];
    float mean = mean_sh, inv = inv_sh;
    __half2* o2 = (__half2*)(out + (size_t)row * D_);
    o2[t * 2    ] = __floats2half2_rn(a * (v.x - mean) * inv + g,
                                      a * (v.y - mean) * inv + g);
    o2[t * 2 + 1] = __floats2half2_rn(a * (v.z - mean) * inv + g,
                                      a * (v.w - mean) * inv + g);
}

// ======================= FP16 tensor-core GEMM ===================================
// CTA tile 128x128, 8 warps each 32x64. BK=32, 4-stage cp.async pipeline.
#define FBK   32
#define FSTR  40                         // halves per smem row
#define FTILE (128 * FSTR)               // 5120 halves per tile
#define FSTG  (2 * FTILE)                // A + BT per stage (halves)
#define F_STAGES 4
#define F_SMEM_BYTES (F_STAGES * FSTG * 2)   // 81920 B

__device__ __forceinline__ void mma_f16(float c[4], const uint32_t a[4],
                                        uint32_t b0, uint32_t b1) {
    asm volatile(
        "mma.sync.aligned.m16n8k16.row.col.f32.f16.f16.f32 "
        "{%0,%1,%2,%3}, {%4,%5,%6,%7}, {%8,%9}, {%0,%1,%2,%3};"
        : "+f"(c[0]), "+f"(c[1]), "+f"(c[2]), "+f"(c[3])
        : "r"(a[0]), "r"(a[1]), "r"(a[2]), "r"(a[3]), "r"(b0), "r"(b1));
}

__device__ __forceinline__ void ldm4(uint32_t r[4], const __half* p) {
    uint32_t a = (uint32_t)__cvta_generic_to_shared(p);
    asm volatile("ldmatrix.sync.aligned.m8n8.x4.shared.b16 {%0,%1,%2,%3}, [%4];"
        : "=r"(r[0]), "=r"(r[1]), "=r"(r[2]), "=r"(r[3]) : "r"(a));
}

__device__ __forceinline__ void ldm4t(uint32_t r[4], const __half* p) {
    uint32_t a = (uint32_t)__cvta_generic_to_shared(p);
    asm volatile("ldmatrix.sync.aligned.m8n8.x4.trans.shared.b16 {%0,%1,%2,%3}, [%4];"
        : "=r"(r[0]), "=r"(r[1]), "=r"(r[2]), "=r"(r[3]) : "r"(a));
}

__device__ __forceinline__ void cp16(void* smem_dst, const void* gsrc) {
    uint32_t s = (uint32_t)__cvta_generic_to_shared(smem_dst);
    asm volatile("cp.async.cg.shared.global [%0], [%1], 16;\n" :: "r"(s), "l"(gsrc));
}

// shared fp16 GEMM mainloop
__device__ __forceinline__ void gemm_core_f16(const __half* __restrict__ A,
                                              const __half* __restrict__ BT,
                                              __half* sm, int bx, int by, int Kdim,
                                              float acc[2][8][4]) {
    int t = threadIdx.x;
    int lane = t & 31, warp = t >> 5;
    int wm = warp >> 1, wn = warp & 1;
    const int nk = Kdim / FBK;

    int rA = (lane & 7) + ((lane >> 3) & 1) * 8;
    int kA = ((lane >> 4) & 1) * 8;
    int rB = (lane & 7) + ((lane >> 4) & 1) * 8;
    int kB = ((lane >> 3) & 1) * 8;

    auto prefetch = [&](int stage, int k0) {
        __half* ab = sm + stage * FSTG;
        __half* bb = ab + FTILE;
        #pragma unroll
        for (int i = 0; i < 2; i++) {
            int lin = t + i * 256;
            int r = lin >> 2, ch = (lin & 3) * 8;
            cp16(ab + r * FSTR + ch, A  + (size_t)(by * 128 + r) * Kdim + k0 + ch);
            cp16(bb + r * FSTR + ch, BT + (size_t)(bx * 128 + r) * Kdim + k0 + ch);
        }
    };

    #pragma unroll
    for (int s = 0; s < F_STAGES; s++) {
        prefetch(s, s * FBK);
        asm volatile("cp.async.commit_group;" ::: "memory");
    }

    for (int kt = 0; kt < nk; kt++) {
        asm volatile("cp.async.wait_group %0;" :: "n"(F_STAGES - 2) : "memory");
        __syncthreads();
        if (kt >= 1) {
            int blk = kt - 1 + F_STAGES;
            if (blk < nk) prefetch((kt - 1) % F_STAGES, blk * FBK);
            asm volatile("cp.async.commit_group;" ::: "memory");
        }

        const __half* pA = sm + (kt % F_STAGES) * FSTG;
        const __half* pB = pA + FTILE;

        #pragma unroll
        for (int kk = 0; kk < 2; kk++) {
            int k16 = kk * 16;
            uint32_t af[2][4];
            #pragma unroll
            for (int mt = 0; mt < 2; mt++)
                ldm4(af[mt], pA + (wm * 32 + mt * 16 + rA) * FSTR + k16 + kA);
            uint32_t bf[4][4];
            #pragma unroll
            for (int p = 0; p < 4; p++)
                ldm4(bf[p], pB + (wn * 64 + p * 16 + rB) * FSTR + k16 + kB);
            #pragma unroll
            for (int nt = 0; nt < 8; nt++) {
                uint32_t b0 = bf[nt >> 1][(nt & 1) * 2];
                uint32_t b1 = bf[nt >> 1][(nt & 1) * 2 + 1];
                mma_f16(acc[0][nt], af[0], b0, b1);
                mma_f16(acc[1][nt], af[1], b0, b1);
            }
        }
    }
}

// EPI 1: bias+relu -> fp16 C.  EPI 2: bias + fp32 residual -> fp32 C.
template<int EPI>
__global__ void __launch_bounds__(256, 2)
gemm_f16(const __half* __restrict__ A,
         const __half* __restrict__ BT,
         const float* __restrict__ bias,
         const float* __restrict__ res,
         void* __restrict__ Cv,
         int Ndim, int Kdim) {
    extern __shared__ __half smh[];
    int bx = blockIdx.x, by = blockIdx.y;
    int lane = threadIdx.x & 31, warp = threadIdx.x >> 5;
    int wm = warp >> 1, wn = warp & 1;
    int gid = lane >> 2, tig = lane & 3;

    float acc[2][8][4];
    #pragma unroll
    for (int mt = 0; mt < 2; mt++)
        #pragma unroll
        for (int nt = 0; nt < 8; nt++)
            #pragma unroll
            for (int c = 0; c < 4; c++) acc[mt][nt][c] = 0.f;

    gemm_core_f16(A, BT, smh, bx, by, Kdim, acc);

    #pragma unroll
    for (int mt = 0; mt < 2; mt++) {
        #pragma unroll
        for (int nt = 0; nt < 8; nt++) {
            #pragma unroll
            for (int half = 0; half < 2; half++) {
                int row = by * 128 + wm * 32 + mt * 16 + gid + half * 8;
                int col = bx * 128 + wn * 64 + nt * 8 + tig * 2;
                float vx = acc[mt][nt][half * 2 + 0] + bias[col];
                float vy = acc[mt][nt][half * 2 + 1] + bias[col + 1];
                if (EPI == 1) {
                    __half2* C = (__half2*)Cv;
                    C[((size_t)row * Ndim + col) >> 1] =
                        __floats2half2_rn(fmaxf(vx, 0.f), fmaxf(vy, 0.f));
                } else {
                    float* C = (float*)Cv;
                    float2 r = *(const float2*)(res + (size_t)row * Ndim + col);
                    *(float2*)(C + (size_t)row * Ndim + col)
                        = make_float2(vx + r.x, vy + r.y);
                }
            }
        }
    }
}

// fused QKV: grid.z in {0,1,2}; fp16 permuted output; Q (z==0) pre-scaled by 0.125
__global__ void __launch_bounds__(256, 2)
gemm_qkv(const __half* __restrict__ A,
         const __half* __restrict__ WTbase,
         const float* __restrict__ bq, const float* __restrict__ bk,
         const float* __restrict__ bv,
         __half* __restrict__ qo, __half* __restrict__ ko, __half* __restrict__ vo) {
    extern __shared__ __half smh[];
    int bx = blockIdx.x, by = blockIdx.y, z = blockIdx.z;
    int lane = threadIdx.x & 31, warp = threadIdx.x >> 5;
    int wm = warp >> 1, wn = warp & 1;
    int gid = lane >> 2, tig = lane & 3;

    const __half* BT  = WTbase + (size_t)z * D_ * D_;
    const float* bias = (z == 0) ? bq : (z == 1) ? bk : bv;
    __half*      C    = (z == 0) ? qo : (z == 1) ? ko : vo;
    float scale = (z == 0) ? 0.125f : 1.0f;

    float acc[2][8][4];
    #pragma unroll
    for (int mt = 0; mt < 2; mt++)
        #pragma unroll
        for (int nt = 0; nt < 8; nt++)
            #pragma unroll
            for (int c = 0; c < 4; c++) acc[mt][nt][c] = 0.f;

    gemm_core_f16(A, BT, smh, bx, by, D_, acc);

    #pragma unroll
    for (int mt = 0; mt < 2; mt++) {
        #pragma unroll
        for (int nt = 0; nt < 8; nt++) {
            #pragma unroll
            for (int half = 0; half < 2; half++) {
                int row = by * 128 + wm * 32 + mt * 16 + gid + half * 8;
                int col = bx * 128 + wn * 64 + nt * 8 + tig * 2;
                float vx = (acc[mt][nt][half * 2 + 0] + bias[col    ]) * scale;
                float vy = (acc[mt][nt][half * 2 + 1] + bias[col + 1]) * scale;
                int bb = row / S_, s = row % S_;
                int hh = col >> 6, dd = col & 63;
                *(__half2*)(C + ((((size_t)bb * H_ + hh) * S_) + s) * DK_ + dd)
                    = __floats2half2_rn(vx, vy);
            }
        }
    }
}

// ================= flash attention, FP16 mma, P-in-register, async KV ============
// grid: (S/128, B*H), block 256 (8 warps), warp = 16 q-rows x 64 dims.
// KV tile = 64 keys, double-buffered cp.async. P never touches smem: the S-mma
// C-fragment layout IS the PV-mma A-fragment layout (FA2 register trick).
#define FA_STR 72
#define FA_KVS (64 * FA_STR)                 // halves per K or V tile
#define FA_SMEM_BYTES ((128 * FA_STR + 2 * 2 * FA_KVS) * 2)   // Q + 2 stages x (K,V)

__global__ void __launch_bounds__(256, 2)
flash_attn_f16(const __half* __restrict__ Q,
               const __half* __restrict__ K,
               const __half* __restrict__ V,
               __half* __restrict__ ctx) {
    extern __shared__ __half smh[];
    __half* smQ  = smh;                       // [128][72]
    __half* smKV = smQ + 128 * FA_STR;        // 2 stages x { K[64][72], V[64][72] }

    int tid = threadIdx.x;
    int lane = tid & 31, wq = tid >> 5;
    int gid = lane >> 2, tig = lane & 3;
    int bh = blockIdx.y, qt = blockIdx.x;
    int qr = wq * 16;

    int rA = (lane & 7) + ((lane >> 3) & 1) * 8;
    int kA = ((lane >> 4) & 1) * 8;
    int rB = (lane & 7) + ((lane >> 4) & 1) * 8;
    int kB = ((lane >> 3) & 1) * 8;
    int rV = (lane & 7) + ((lane >> 3) & 1) * 8;
    int cV = ((lane >> 4) & 1) * 8;

    const __half* Qp = Q + ((size_t)bh * S_ + qt * 128) * DK_;
    const __half* Kp = K + (size_t)bh * S_ * DK_;
    const __half* Vp = V + (size_t)bh * S_ * DK_;

    // async prefetch of KV tile kt into stage
    auto prefetchKV = [&](int stage, int kt) {
        const __half* Kt = Kp + (size_t)kt * 64 * DK_;
        const __half* Vt = Vp + (size_t)kt * 64 * DK_;
        __half* kb = smKV + stage * 2 * FA_KVS;
        __half* vb = kb + FA_KVS;
        #pragma unroll
        for (int i = 0; i < 2; i++) {
            int lin = tid + i * 256;               // 0..511
            int r = lin >> 3, c8 = (lin & 7) * 8;
            cp16(kb + r * FA_STR + c8, Kt + (size_t)r * DK_ + c8);
            cp16(vb + r * FA_STR + c8, Vt + (size_t)r * DK_ + c8);
        }
    };

    // Q tile (already scaled by producer)
    for (int idx = tid; idx < 128 * 8; idx += 256) {
        int r = idx >> 3, c8 = (idx & 7) * 8;
        *(int4*)(smQ + r * FA_STR + c8) = *(const int4*)(Qp + (size_t)r * DK_ + c8);
    }

    prefetchKV(0, 0);
    asm volatile("cp.async.commit_group;" ::: "memory");

    float m0 = -1e30f, m1 = -1e30f, l0 = 0.f, l1 = 0.f;
    float o[8][4];
    #pragma unroll
    for (int nt = 0; nt < 8; nt++)
        #pragma unroll
        for (int c = 0; c < 4; c++) o[nt][c] = 0.f;

    const int NT = S_ / 64;
    for (int kt = 0; kt < NT; kt++) {
        asm volatile("cp.async.wait_group 0;" ::: "memory");
        __syncthreads();
        if (kt + 1 < NT) {
            prefetchKV((kt + 1) & 1, kt + 1);
            asm volatile("cp.async.commit_group;" ::: "memory");
        }
        const __half* pK = smKV + (kt & 1) * 2 * FA_KVS;
        const __half* pV = pK + FA_KVS;

        // ---- S = Q @ K^T ----
        float sacc[8][4];
        #pragma unroll
        for (int nt = 0; nt < 8; nt++)
            #pragma unroll
            for (int c = 0; c < 4; c++) sacc[nt][c] = 0.f;
        #pragma unroll
        for (int kk = 0; kk < 4; kk++) {
            int k16 = kk * 16;
            uint32_t af[4];
            ldm4(af, smQ + (qr + rA) * FA_STR + k16 + kA);
            uint32_t bfm[4][4];
            #pragma unroll
            for (int p = 0; p < 4; p++)
                ldm4(bfm[p], pK + (p * 16 + rB) * FA_STR + k16 + kB);
            #pragma unroll
            for (int nt = 0; nt < 8; nt++)
                mma_f16(sacc[nt], af, bfm[nt >> 1][(nt & 1) * 2],
                                      bfm[nt >> 1][(nt & 1) * 2 + 1]);
        }

        // ---- online softmax in registers ----
        float tmx0 = -1e30f, tmx1 = -1e30f;
        #pragma unroll
        for (int nt = 0; nt < 8; nt++) {
            tmx0 = fmaxf(tmx0, fmaxf(sacc[nt][0], sacc[nt][1]));
            tmx1 = fmaxf(tmx1, fmaxf(sacc[nt][2], sacc[nt][3]));
        }
        tmx0 = fmaxf(tmx0, __shfl_xor_sync(0xFFFFFFFFu, tmx0, 1));
        tmx0 = fmaxf(tmx0, __shfl_xor_sync(0xFFFFFFFFu, tmx0, 2));
        tmx1 = fmaxf(tmx1, __shfl_xor_sync(0xFFFFFFFFu, tmx1, 1));
        tmx1 = fmaxf(tmx1, __shfl_xor_sync(0xFFFFFFFFu, tmx1, 2));
        float nm0 = fmaxf(m0, tmx0), nm1 = fmaxf(m1, tmx1);
        float sum0 = 0.f, sum1 = 0.f;
        #pragma unroll
        for (int nt = 0; nt < 8; nt++) {
            sacc[nt][0] = __expf(sacc[nt][0] - nm0);
            sacc[nt][1] = __expf(sacc[nt][1] - nm0);
            sacc[nt][2] = __expf(sacc[nt][2] - nm1);
            sacc[nt][3] = __expf(sacc[nt][3] - nm1);
            sum0 += sacc[nt][0] + sacc[nt][1];
            sum1 += sacc[nt][2] + sacc[nt][3];
        }
        sum0 += __shfl_xor_sync(0xFFFFFFFFu, sum0, 1);
        sum0 += __shfl_xor_sync(0xFFFFFFFFu, sum0, 2);
        sum1 += __shfl_xor_sync(0xFFFFFFFFu, sum1, 1);
        sum1 += __shfl_xor_sync(0xFFFFFFFFu, sum1, 2);
        float rf0 = __expf(m0 - nm0), rf1 = __expf(m1 - nm1);
        m0 = nm0; m1 = nm1;
        l0 = l0 * rf0 + sum0;
        l1 = l1 * rf1 + sum1;
        #pragma unroll
        for (int nt = 0; nt < 8; nt++) {
            o[nt][0] *= rf0; o[nt][1] *= rf0;
            o[nt][2] *= rf1; o[nt][3] *= rf1;
        }

        // ---- O += P @ V : P direct from registers (C-layout == A-layout) ----
        #pragma unroll
        for (int kk = 0; kk < 4; kk++) {
            int k16 = kk * 16;
            uint32_t af[4];
            af[0] = packh2(sacc[2 * kk    ][0], sacc[2 * kk    ][1]);
            af[1] = packh2(sacc[2 * kk    ][2], sacc[2 * kk    ][3]);
            af[2] = packh2(sacc[2 * kk + 1][0], sacc[2 * kk + 1][1]);
            af[3] = packh2(sacc[2 * kk + 1][2], sacc[2 * kk + 1][3]);
            uint32_t bfm[4][4];
            #pragma unroll
            for (int p = 0; p < 4; p++)
                ldm4t(bfm[p], pV + (k16 + rV) * FA_STR + p * 16 + cV);
            #pragma unroll
            for (int nt = 0; nt < 8; nt++)
                mma_f16(o[nt], af, bfm[nt >> 1][(nt & 1) * 2],
                                   bfm[nt >> 1][(nt & 1) * 2 + 1]);
        }
    }

    float inv0 = 1.f / l0, inv1 = 1.f / l1;
    int b = bh >> 4, h = bh & 15;
    int s0 = qt * 128 + qr + gid;
    #pragma unroll
    for (int nt = 0; nt < 8; nt++) {
        int col = h * DK_ + nt * 8 + tig * 2;
        *(__half2*)(ctx + (size_t)(b * S_ + s0    ) * D_ + col)
            = __floats2half2_rn(o[nt][0] * inv0, o[nt][1] * inv0);
        *(__half2*)(ctx + (size_t)(b * S_ + s0 + 8) * D_ + col)
            = __floats2half2_rn(o[nt][2] * inv1, o[nt][3] * inv1);
    }
}

// ---------------- launch ----------------------------------------------------------
extern "C" void kernel_launch(void* const* d_in, const int* in_sizes, int n_in,
                              void* d_out, int out_size) {
    const float* x  = (const float*)d_in[0];
    // d_in[1] = src_mask (no-op in reference, ignored)
    const float* Wq = (const float*)d_in[2];
    const float* bq = (const float*)d_in[3];
    const float* Wk = (const float*)d_in[4];
    const float* bk = (const float*)d_in[5];
    const float* Wv = (const float*)d_in[6];
    const float* bv = (const float*)d_in[7];
    const float* Wo = (const float*)d_in[8];
    const float* bo = (const float*)d_in[9];
    const float* W1 = (const float*)d_in[10];
    const float* b1 = (const float*)d_in[11];
    const float* W2 = (const float*)d_in[12];
    const float* b2 = (const float*)d_in[13];
    const float* a1 = (const float*)d_in[14];
    const float* g1 = (const float*)d_in[15];
    const float* a2 = (const float*)d_in[16];
    const float* g2 = (const float*)d_in[17];
    float* out = (float*)d_out;

    __half *hbuf, *qb, *kb, *vb, *ctx, *ffb, *wt;
    float *x2;
    cudaGetSymbolAddress((void**)&hbuf, g_h);
    cudaGetSymbolAddress((void**)&qb,   g_q);
    cudaGetSymbolAddress((void**)&kb,   g_k);
    cudaGetSymbolAddress((void**)&vb,   g_v);
    cudaGetSymbolAddress((void**)&ctx,  g_ctx);
    cudaGetSymbolAddress((void**)&x2,   g_x2);
    cudaGetSymbolAddress((void**)&ffb,  g_ff);
    cudaGetSymbolAddress((void**)&wt,   g_wt);

    __half* WqT = wt;                                // WqT|WkT|WvT contiguous
    __half* WkT = WqT + (size_t)D_ * D_;
    __half* WvT = WkT + (size_t)D_ * D_;
    __half* WoT = WvT + (size_t)D_ * D_;
    __half* W1T = WoT + (size_t)D_ * D_;             // [DFF][D]
    __half* W2T = W1T + (size_t)D_ * DFF_;           // [D][DFF]

    cudaFuncSetAttribute(flash_attn_f16,
                         cudaFuncAttributeMaxDynamicSharedMemorySize, FA_SMEM_BYTES);
    cudaFuncSetAttribute(gemm_f16<1>, cudaFuncAttributeMaxDynamicSharedMemorySize, F_SMEM_BYTES);
    cudaFuncSetAttribute(gemm_f16<2>, cudaFuncAttributeMaxDynamicSharedMemorySize, F_SMEM_BYTES);
    cudaFuncSetAttribute(gemm_qkv,    cudaFuncAttributeMaxDynamicSharedMemorySize, F_SMEM_BYTES);

    // 0. all weight transposes -> fp16, single launch
    transpose_all<<<12288, dim3(32, 8)>>>(Wq, Wk, Wv, Wo, W1, W2,
                                          WqT, WkT, WvT, WoT, W1T, W2T);

    dim3 gD(D_ / 128, M_ / 128);        // (8, 32)
    dim3 gQKV(D_ / 128, M_ / 128, 3);   // fused QKV
    dim3 gF(DFF_ / 128, M_ / 128);      // (32, 32)

    // 1. LN1 -> fp16
    layernorm_kernel<<<M_, 256>>>(x, a1, g1, hbuf);
    // 2. QKV projections (fp16 gemm, fp16 permuted store, Q pre-scaled)
    gemm_qkv<<<gQKV, 256, F_SMEM_BYTES>>>(hbuf, WqT, bq, bk, bv, qb, kb, vb);
    // 3. attention (fp16 tensor-core, P-in-register, async KV)
    flash_attn_f16<<<dim3(S_ / 128, B_ * H_), 256, FA_SMEM_BYTES>>>(qb, kb, vb, ctx);
    // 4. O projection + residual 1 (fp32 exact residual)
    gemm_f16<2><<<gD, 256, F_SMEM_BYTES>>>(ctx, WoT, bo, x, x2, D_, D_);
    // 5. LN2 -> fp16
    layernorm_kernel<<<M_, 256>>>(x2, a2, g2, hbuf);
    // 6. FFN up + ReLU -> fp16
    gemm_f16<1><<<gF, 256, F_SMEM_BYTES>>>(hbuf, W1T, b1, nullptr, ffb, DFF_, D_);
    // 7. FFN down + residual 2 -> output (fp32)
    gemm_f16<2><<<gD, 256, F_SMEM_BYTES>>>(ffb, W2T, b2, x2, out, D_, DFF_);
}

// round 16
// speedup vs baseline: 1.2050x; 1.0075x over previous
#include <cuda_runtime.h>
#include <cuda_fp16.h>
#include <cstdint>
#include <stdint.h>
#include <math.h>

#define B_   2
#define S_   2048
#define D_   1024
#define H_   16
#define DK_  64
#define DFF_ 4096
#define M_   (B_ * S_)      // 4096 rows
#define EPS_ 1e-6f
#define LOG2E_ 1.4426950408889634f

// ---------------- scratch (device globals; no allocation allowed) ----------------
__device__ __half g_h  [(size_t)M_ * D_];    // LN output (fp16, reused for LN2)
__device__ __half g_q  [(size_t)M_ * D_];    // (b,h,s,d) fp16, pre-scaled 0.125*log2e
__device__ __half g_k  [(size_t)M_ * D_];    // (b,h,s,d) fp16
__device__ __half g_v  [(size_t)M_ * D_];    // (b,h,s,d) fp16
__device__ __half g_ctx[(size_t)M_ * D_];    // (m, h*DK+d) fp16
__device__ float  g_x2 [(size_t)M_ * D_];    // residual-1 output (exact fp32)
__device__ __half g_ff [(size_t)M_ * DFF_];  // relu(h2@W1+b1), fp16
// transposed fp16 weights: WqT,WkT,WvT (contiguous), WoT, W1T (DFF*D), W2T (D*DFF)
__device__ __half g_wt [(size_t)4 * D_ * D_ + 2 * (size_t)D_ * DFF_];

__device__ __forceinline__ uint32_t fb(float f) { return __float_as_uint(f); }
__device__ __forceinline__ uint32_t packh2(float lo, float hi) {
    __half2 h = __floats2half2_rn(lo, hi);
    return *(uint32_t*)&h;
}
__device__ __forceinline__ float ex2(float x) {     // raw EX2, no pre-multiply
    float r;
    asm("ex2.approx.f32 %0, %1;" : "=f"(r) : "f"(x));
    return r;
}

// ------- fused weight transposes -> fp16: one launch, flattened block ranges -----
__global__ void transpose_all(const float* __restrict__ Wq, const float* __restrict__ Wk,
                              const float* __restrict__ Wv, const float* __restrict__ Wo,
                              const float* __restrict__ W1, const float* __restrict__ W2,
                              __half* __restrict__ WqT, __half* __restrict__ WkT,
                              __half* __restrict__ WvT, __half* __restrict__ WoT,
                              __half* __restrict__ W1T, __half* __restrict__ W2T) {
    int bid = blockIdx.x;
    const float* W; __half* WT; int K, N, local;
    if      (bid <  1024) { W = Wq; WT = WqT; K = D_;   N = D_;   local = bid; }
    else if (bid <  2048) { W = Wk; WT = WkT; K = D_;   N = D_;   local = bid - 1024; }
    else if (bid <  3072) { W = Wv; WT = WvT; K = D_;   N = D_;   local = bid - 2048; }
    else if (bid <  4096) { W = Wo; WT = WoT; K = D_;   N = D_;   local = bid - 3072; }
    else if (bid <  8192) { W = W1; WT = W1T; K = D_;   N = DFF_; local = bid - 4096; }
    else                  { W = W2; WT = W2T; K = DFF_; N = D_;   local = bid - 8192; }
    int nbx = N / 32;
    int by = local / nbx, bx = local % nbx;

    __shared__ float tile[32][33];
    int k0 = by * 32, n0 = bx * 32;
    int tx = threadIdx.x, ty = threadIdx.y;        // (32, 8)
    #pragma unroll
    for (int i = 0; i < 4; i++)
        tile[ty + i * 8][tx] = W[(size_t)(k0 + ty + i * 8) * N + n0 + tx];
    __syncthreads();
    #pragma unroll
    for (int i = 0; i < 4; i++)
        WT[(size_t)(n0 + ty + i * 8) * K + k0 + tx] = __float2half(tile[tx][ty + i * 8]);
}

// -------- layernorm: alpha*(x-mean)/(std+eps)+beta, unbiased std, fp16 output ----
__global__ void layernorm_kernel(const float* __restrict__ x,
                                 const float* __restrict__ alpha,
                                 const float* __restrict__ beta,
                                 __half* __restrict__ out) {
    int row = blockIdx.x;
    int t = threadIdx.x;                       // 256 threads, 4 elems each (D=1024)
    const float4* xr = (const float4*)(x + (size_t)row * D_);
    float4 v = xr[t];
    float s  = v.x + v.y + v.z + v.w;
    float sq = v.x*v.x + v.y*v.y + v.z*v.z + v.w*v.w;
    #pragma unroll
    for (int o = 16; o > 0; o >>= 1) {
        s  += __shfl_xor_sync(0xFFFFFFFFu, s,  o);
        sq += __shfl_xor_sync(0xFFFFFFFFu, sq, o);
    }
    __shared__ float ss[8], sqs[8];
    __shared__ float mean_sh, inv_sh;
    int w = t >> 5;
    if ((t & 31) == 0) { ss[w] = s; sqs[w] = sq; }
    __syncthreads();
    if (t == 0) {
        float S = 0.f, SQ = 0.f;
        #pragma unroll
        for (int i = 0; i < 8; i++) { S += ss[i]; SQ += sqs[i]; }
        float mean = S / (float)D_;
        float var  = (SQ - (float)D_ * mean * mean) / (float)(D_ - 1);
        float sd   = sqrtf(fmaxf(var, 0.f));
        mean_sh = mean;
        inv_sh  = 1.f / (sd + EPS_);
    }
    __syncthreads();
    float a = alpha[0], g = beta[0];
    float mean = mean_sh, inv = inv_sh;
    __half2* o2 = (__half2*)(out + (size_t)row * D_);
    o2[t * 2    ] = __floats2half2_rn(a * (v.x - mean) * inv + g,
                                      a * (v.y - mean) * inv + g);
    o2[t * 2 + 1] = __floats2half2_rn(a * (v.z - mean) * inv + g,
                                      a * (v.w - mean) * inv + g);
}

// ======================= FP16 tensor-core GEMM ===================================
// CTA tile 128x128, 8 warps each 32x64. BK=32, 4-stage cp.async pipeline.
#define FBK   32
#define FSTR  40                         // halves per smem row
#define FTILE (128 * FSTR)               // 5120 halves per tile
#define FSTG  (2 * FTILE)                // A + BT per stage (halves)
#define F_STAGES 4
#define F_SMEM_BYTES (F_STAGES * FSTG * 2)   // 81920 B

__device__ __forceinline__ void mma_f16(float c[4], const uint32_t a[4],
                                        uint32_t b0, uint32_t b1) {
    asm volatile(
        "mma.sync.aligned.m16n8k16.row.col.f32.f16.f16.f32 "
        "{%0,%1,%2,%3}, {%4,%5,%6,%7}, {%8,%9}, {%0,%1,%2,%3};"
        : "+f"(c[0]), "+f"(c[1]), "+f"(c[2]), "+f"(c[3])
        : "r"(a[0]), "r"(a[1]), "r"(a[2]), "r"(a[3]), "r"(b0), "r"(b1));
}

__device__ __forceinline__ void ldm4(uint32_t r[4], const __half* p) {
    uint32_t a = (uint32_t)__cvta_generic_to_shared(p);
    asm volatile("ldmatrix.sync.aligned.m8n8.x4.shared.b16 {%0,%1,%2,%3}, [%4];"
        : "=r"(r[0]), "=r"(r[1]), "=r"(r[2]), "=r"(r[3]) : "r"(a));
}

__device__ __forceinline__ void ldm4t(uint32_t r[4], const __half* p) {
    uint32_t a = (uint32_t)__cvta_generic_to_shared(p);
    asm volatile("ldmatrix.sync.aligned.m8n8.x4.trans.shared.b16 {%0,%1,%2,%3}, [%4];"
        : "=r"(r[0]), "=r"(r[1]), "=r"(r[2]), "=r"(r[3]) : "r"(a));
}

__device__ __forceinline__ void cp16(void* smem_dst, const void* gsrc) {
    uint32_t s = (uint32_t)__cvta_generic_to_shared(smem_dst);
    asm volatile("cp.async.cg.shared.global [%0], [%1], 16;\n" :: "r"(s), "l"(gsrc));
}

// shared fp16 GEMM mainloop
__device__ __forceinline__ void gemm_core_f16(const __half* __restrict__ A,
                                              const __half* __restrict__ BT,
                                              __half* sm, int bx, int by, int Kdim,
                                              float acc[2][8][4]) {
    int t = threadIdx.x;
    int lane = t & 31, warp = t >> 5;
    int wm = warp >> 1, wn = warp & 1;
    const int nk = Kdim / FBK;

    int rA = (lane & 7) + ((lane >> 3) & 1) * 8;
    int kA = ((lane >> 4) & 1) * 8;
    int rB = (lane & 7) + ((lane >> 4) & 1) * 8;
    int kB = ((lane >> 3) & 1) * 8;

    auto prefetch = [&](int stage, int k0) {
        __half* ab = sm + stage * FSTG;
        __half* bb = ab + FTILE;
        #pragma unroll
        for (int i = 0; i < 2; i++) {
            int lin = t + i * 256;
            int r = lin >> 2, ch = (lin & 3) * 8;
            cp16(ab + r * FSTR + ch, A  + (size_t)(by * 128 + r) * Kdim + k0 + ch);
            cp16(bb + r * FSTR + ch, BT + (size_t)(bx * 128 + r) * Kdim + k0 + ch);
        }
    };

    #pragma unroll
    for (int s = 0; s < F_STAGES; s++) {
        prefetch(s, s * FBK);
        asm volatile("cp.async.commit_group;" ::: "memory");
    }

    for (int kt = 0; kt < nk; kt++) {
        asm volatile("cp.async.wait_group %0;" :: "n"(F_STAGES - 2) : "memory");
        __syncthreads();
        if (kt >= 1) {
            int blk = kt - 1 + F_STAGES;
            if (blk < nk) prefetch((kt - 1) % F_STAGES, blk * FBK);
            asm volatile("cp.async.commit_group;" ::: "memory");
        }

        const __half* pA = sm + (kt % F_STAGES) * FSTG;
        const __half* pB = pA + FTILE;

        #pragma unroll
        for (int kk = 0; kk < 2; kk++) {
            int k16 = kk * 16;
            uint32_t af[2][4];
            #pragma unroll
            for (int mt = 0; mt < 2; mt++)
                ldm4(af[mt], pA + (wm * 32 + mt * 16 + rA) * FSTR + k16 + kA);
            uint32_t bf[4][4];
            #pragma unroll
            for (int p = 0; p < 4; p++)
                ldm4(bf[p], pB + (wn * 64 + p * 16 + rB) * FSTR + k16 + kB);
            #pragma unroll
            for (int nt = 0; nt < 8; nt++) {
                uint32_t b0 = bf[nt >> 1][(nt & 1) * 2];
                uint32_t b1 = bf[nt >> 1][(nt & 1) * 2 + 1];
                mma_f16(acc[0][nt], af[0], b0, b1);
                mma_f16(acc[1][nt], af[1], b0, b1);
            }
        }
    }
}

// EPI 1: bias+relu -> fp16 C.  EPI 2: bias + fp32 residual -> fp32 C.
template<int EPI>
__global__ void __launch_bounds__(256, 2)
gemm_f16(const __half* __restrict__ A,
         const __half* __restrict__ BT,
         const float* __restrict__ bias,
         const float* __restrict__ res,
         void* __restrict__ Cv,
         int Ndim, int Kdim) {
    extern __shared__ __half smh[];
    int bx = blockIdx.x, by = blockIdx.y;
    int lane = threadIdx.x & 31, warp = threadIdx.x >> 5;
    int wm = warp >> 1, wn = warp & 1;
    int gid = lane >> 2, tig = lane & 3;

    float acc[2][8][4];
    #pragma unroll
    for (int mt = 0; mt < 2; mt++)
        #pragma unroll
        for (int nt = 0; nt < 8; nt++)
            #pragma unroll
            for (int c = 0; c < 4; c++) acc[mt][nt][c] = 0.f;

    gemm_core_f16(A, BT, smh, bx, by, Kdim, acc);

    #pragma unroll
    for (int mt = 0; mt < 2; mt++) {
        #pragma unroll
        for (int nt = 0; nt < 8; nt++) {
            #pragma unroll
            for (int half = 0; half < 2; half++) {
                int row = by * 128 + wm * 32 + mt * 16 + gid + half * 8;
                int col = bx * 128 + wn * 64 + nt * 8 + tig * 2;
                float vx = acc[mt][nt][half * 2 + 0] + bias[col];
                float vy = acc[mt][nt][half * 2 + 1] + bias[col + 1];
                if (EPI == 1) {
                    __half2* C = (__half2*)Cv;
                    C[((size_t)row * Ndim + col) >> 1] =
                        __floats2half2_rn(fmaxf(vx, 0.f), fmaxf(vy, 0.f));
                } else {
                    float* C = (float*)Cv;
                    float2 r = *(const float2*)(res + (size_t)row * Ndim + col);
                    *(float2*)(C + (size_t)row * Ndim + col)
                        = make_float2(vx + r.x, vy + r.y);
                }
            }
        }
    }
}

// fused QKV: grid.z in {0,1,2}; fp16 permuted output; Q scaled by 0.125*log2e
__global__ void __launch_bounds__(256, 2)
gemm_qkv(const __half* __restrict__ A,
         const __half* __restrict__ WTbase,
         const float* __restrict__ bq, const float* __restrict__ bk,
         const float* __restrict__ bv,
         __half* __restrict__ qo, __half* __restrict__ ko, __half* __restrict__ vo) {
    extern __shared__ __half smh[];
    int bx = blockIdx.x, by = blockIdx.y, z = blockIdx.z;
    int lane = threadIdx.x & 31, warp = threadIdx.x >> 5;
    int wm = warp >> 1, wn = warp & 1;
    int gid = lane >> 2, tig = lane & 3;

    const __half* BT  = WTbase + (size_t)z * D_ * D_;
    const float* bias = (z == 0) ? bq : (z == 1) ? bk : bv;
    __half*      C    = (z == 0) ? qo : (z == 1) ? ko : vo;
    float scale = (z == 0) ? 0.125f * LOG2E_ : 1.0f;

    float acc[2][8][4];
    #pragma unroll
    for (int mt = 0; mt < 2; mt++)
        #pragma unroll
        for (int nt = 0; nt < 8; nt++)
            #pragma unroll
            for (int c = 0; c < 4; c++) acc[mt][nt][c] = 0.f;

    gemm_core_f16(A, BT, smh, bx, by, D_, acc);

    #pragma unroll
    for (int mt = 0; mt < 2; mt++) {
        #pragma unroll
        for (int nt = 0; nt < 8; nt++) {
            #pragma unroll
            for (int half = 0; half < 2; half++) {
                int row = by * 128 + wm * 32 + mt * 16 + gid + half * 8;
                int col = bx * 128 + wn * 64 + nt * 8 + tig * 2;
                float vx = (acc[mt][nt][half * 2 + 0] + bias[col    ]) * scale;
                float vy = (acc[mt][nt][half * 2 + 1] + bias[col + 1]) * scale;
                int bb = row / S_, s = row % S_;
                int hh = col >> 6, dd = col & 63;
                *(__half2*)(C + ((((size_t)bb * H_ + hh) * S_) + s) * DK_ + dd)
                    = __floats2half2_rn(vx, vy);
            }
        }
    }
}

// ====== flash attention: FP16 mma, P-in-register, base-2 softmax, 3-stage KV =====
// Scores arrive pre-scaled by log2e (Q producer) -> softmax uses raw EX2.
#define FA_STR 72
#define FA_KVS (64 * FA_STR)                 // halves per K or V tile
#define FA_STAGES 3
#define FA_SMEM_BYTES ((128 * FA_STR + FA_STAGES * 2 * FA_KVS) * 2)   // 73728 B

__global__ void __launch_bounds__(256, 2)
flash_attn_f16(const __half* __restrict__ Q,
               const __half* __restrict__ K,
               const __half* __restrict__ V,
               __half* __restrict__ ctx) {
    extern __shared__ __half smh[];
    __half* smQ  = smh;                       // [128][72]
    __half* smKV = smQ + 128 * FA_STR;        // 3 stages x { K[64][72], V[64][72] }

    int tid = threadIdx.x;
    int lane = tid & 31, wq = tid >> 5;
    int gid = lane >> 2, tig = lane & 3;
    int bh = blockIdx.y, qt = blockIdx.x;
    int qr = wq * 16;

    int rA = (lane & 7) + ((lane >> 3) & 1) * 8;
    int kA = ((lane >> 4) & 1) * 8;
    int rB = (lane & 7) + ((lane >> 4) & 1) * 8;
    int kB = ((lane >> 3) & 1) * 8;
    int rV = (lane & 7) + ((lane >> 3) & 1) * 8;
    int cV = ((lane >> 4) & 1) * 8;

    const __half* Qp = Q + ((size_t)bh * S_ + qt * 128) * DK_;
    const __half* Kp = K + (size_t)bh * S_ * DK_;
    const __half* Vp = V + (size_t)bh * S_ * DK_;

    auto prefetchKV = [&](int stage, int kt) {
        const __half* Kt = Kp + (size_t)kt * 64 * DK_;
        const __half* Vt = Vp + (size_t)kt * 64 * DK_;
        __half* kb = smKV + stage * 2 * FA_KVS;
        __half* vb = kb + FA_KVS;
        #pragma unroll
        for (int i = 0; i < 2; i++) {
            int lin = tid + i * 256;               // 0..511
            int r = lin >> 3, c8 = (lin & 7) * 8;
            cp16(kb + r * FA_STR + c8, Kt + (size_t)r * DK_ + c8);
            cp16(vb + r * FA_STR + c8, Vt + (size_t)r * DK_ + c8);
        }
    };

    // Q tile (pre-scaled by 0.125*log2e at producer)
    for (int idx = tid; idx < 128 * 8; idx += 256) {
        int r = idx >> 3, c8 = (idx & 7) * 8;
        *(int4*)(smQ + r * FA_STR + c8) = *(const int4*)(Qp + (size_t)r * DK_ + c8);
    }

    prefetchKV(0, 0);
    asm volatile("cp.async.commit_group;" ::: "memory");
    prefetchKV(1, 1);
    asm volatile("cp.async.commit_group;" ::: "memory");

    float m0 = -1e30f, m1 = -1e30f, l0 = 0.f, l1 = 0.f;
    float o[8][4];
    #pragma unroll
    for (int nt = 0; nt < 8; nt++)
        #pragma unroll
        for (int c = 0; c < 4; c++) o[nt][c] = 0.f;

    const int NT = S_ / 64;
    for (int kt = 0; kt < NT; kt++) {
        asm volatile("cp.async.wait_group 1;" ::: "memory");
        __syncthreads();
        if (kt + 2 < NT) {
            prefetchKV((kt + 2) % FA_STAGES, kt + 2);
            asm volatile("cp.async.commit_group;" ::: "memory");
        }
        const __half* pK = smKV + (kt % FA_STAGES) * 2 * FA_KVS;
        const __half* pV = pK + FA_KVS;

        // ---- S = Q @ K^T  (scores already x log2e) ----
        float sacc[8][4];
        #pragma unroll
        for (int nt = 0; nt < 8; nt++)
            #pragma unroll
            for (int c = 0; c < 4; c++) sacc[nt][c] = 0.f;
        #pragma unroll
        for (int kk = 0; kk < 4; kk++) {
            int k16 = kk * 16;
            uint32_t af[4];
            ldm4(af, smQ + (qr + rA) * FA_STR + k16 + kA);
            uint32_t bfm[4][4];
            #pragma unroll
            for (int p = 0; p < 4; p++)
                ldm4(bfm[p], pK + (p * 16 + rB) * FA_STR + k16 + kB);
            #pragma unroll
            for (int nt = 0; nt < 8; nt++)
                mma_f16(sacc[nt], af, bfm[nt >> 1][(nt & 1) * 2],
                                      bfm[nt >> 1][(nt & 1) * 2 + 1]);
        }

        // ---- base-2 online softmax in registers ----
        float tmx0 = -1e30f, tmx1 = -1e30f;
        #pragma unroll
        for (int nt = 0; nt < 8; nt++) {
            tmx0 = fmaxf(tmx0, fmaxf(sacc[nt][0], sacc[nt][1]));
            tmx1 = fmaxf(tmx1, fmaxf(sacc[nt][2], sacc[nt][3]));
        }
        tmx0 = fmaxf(tmx0, __shfl_xor_sync(0xFFFFFFFFu, tmx0, 1));
        tmx0 = fmaxf(tmx0, __shfl_xor_sync(0xFFFFFFFFu, tmx0, 2));
        tmx1 = fmaxf(tmx1, __shfl_xor_sync(0xFFFFFFFFu, tmx1, 1));
        tmx1 = fmaxf(tmx1, __shfl_xor_sync(0xFFFFFFFFu, tmx1, 2));
        float nm0 = fmaxf(m0, tmx0), nm1 = fmaxf(m1, tmx1);
        float sum0 = 0.f, sum1 = 0.f;
        #pragma unroll
        for (int nt = 0; nt < 8; nt++) {
            sacc[nt][0] = ex2(sacc[nt][0] - nm0);
            sacc[nt][1] = ex2(sacc[nt][1] - nm0);
            sacc[nt][2] = ex2(sacc[nt][2] - nm1);
            sacc[nt][3] = ex2(sacc[nt][3] - nm1);
            sum0 += sacc[nt][0] + sacc[nt][1];
            sum1 += sacc[nt][2] + sacc[nt][3];
        }
        sum0 += __shfl_xor_sync(0xFFFFFFFFu, sum0, 1);
        sum0 += __shfl_xor_sync(0xFFFFFFFFu, sum0, 2);
        sum1 += __shfl_xor_sync(0xFFFFFFFFu, sum1, 1);
        sum1 += __shfl_xor_sync(0xFFFFFFFFu, sum1, 2);
        float rf0 = ex2(m0 - nm0), rf1 = ex2(m1 - nm1);
        m0 = nm0; m1 = nm1;
        l0 = l0 * rf0 + sum0;
        l1 = l1 * rf1 + sum1;
        #pragma unroll
        for (int nt = 0; nt < 8; nt++) {
            o[nt][0] *= rf0; o[nt][1] *= rf0;
            o[nt][2] *= rf1; o[nt][3] *= rf1;
        }

        // ---- O += P @ V : P direct from registers ----
        #pragma unroll
        for (int kk = 0; kk < 4; kk++) {
            int k16 = kk * 16;
            uint32_t af[4];
            af[0] = packh2(sacc[2 * kk    ][0], sacc[2 * kk    ][1]);
            af[1] = packh2(sacc[2 * kk    ][2], sacc[2 * kk    ][3]);
            af[2] = packh2(sacc[2 * kk + 1][0], sacc[2 * kk + 1][1]);
            af[3] = packh2(sacc[2 * kk + 1][2], sacc[2 * kk + 1][3]);
            uint32_t bfm[4][4];
            #pragma unroll
            for (int p = 0; p < 4; p++)
                ldm4t(bfm[p], pV + (k16 + rV) * FA_STR + p * 16 + cV);
            #pragma unroll
            for (int nt = 0; nt < 8; nt++)
                mma_f16(o[nt], af, bfm[nt >> 1][(nt & 1) * 2],
                                   bfm[nt >> 1][(nt & 1) * 2 + 1]);
        }
    }

    float inv0 = 1.f / l0, inv1 = 1.f / l1;
    int b = bh >> 4, h = bh & 15;
    int s0 = qt * 128 + qr + gid;
    #pragma unroll
    for (int nt = 0; nt < 8; nt++) {
        int col = h * DK_ + nt * 8 + tig * 2;
        *(__half2*)(ctx + (size_t)(b * S_ + s0    ) * D_ + col)
            = __floats2half2_rn(o[nt][0] * inv0, o[nt][1] * inv0);
        *(__half2*)(ctx + (size_t)(b * S_ + s0 + 8) * D_ + col)
            = __floats2half2_rn(o[nt][2] * inv1, o[nt][3] * inv1);
    }
}

// ---------------- launch ----------------------------------------------------------
extern "C" void kernel_launch(void* const* d_in, const int* in_sizes, int n_in,
                              void* d_out, int out_size) {
    const float* x  = (const float*)d_in[0];
    // d_in[1] = src_mask (no-op in reference, ignored)
    const float* Wq = (const float*)d_in[2];
    const float* bq = (const float*)d_in[3];
    const float* Wk = (const float*)d_in[4];
    const float* bk = (const float*)d_in[5];
    const float* Wv = (const float*)d_in[6];
    const float* bv = (const float*)d_in[7];
    const float* Wo = (const float*)d_in[8];
    const float* bo = (const float*)d_in[9];
    const float* W1 = (const float*)d_in[10];
    const float* b1 = (const float*)d_in[11];
    const float* W2 = (const float*)d_in[12];
    const float* b2 = (const float*)d_in[13];
    const float* a1 = (const float*)d_in[14];
    const float* g1 = (const float*)d_in[15];
    const float* a2 = (const float*)d_in[16];
    const float* g2 = (const float*)d_in[17];
    float* out = (float*)d_out;

    __half *hbuf, *qb, *kb, *vb, *ctx, *ffb, *wt;
    float *x2;
    cudaGetSymbolAddress((void**)&hbuf, g_h);
    cudaGetSymbolAddress((void**)&qb,   g_q);
    cudaGetSymbolAddress((void**)&kb,   g_k);
    cudaGetSymbolAddress((void**)&vb,   g_v);
    cudaGetSymbolAddress((void**)&ctx,  g_ctx);
    cudaGetSymbolAddress((void**)&x2,   g_x2);
    cudaGetSymbolAddress((void**)&ffb,  g_ff);
    cudaGetSymbolAddress((void**)&wt,   g_wt);

    __half* WqT = wt;                                // WqT|WkT|WvT contiguous
    __half* WkT = WqT + (size_t)D_ * D_;
    __half* WvT = WkT + (size_t)D_ * D_;
    __half* WoT = WvT + (size_t)D_ * D_;
    __half* W1T = WoT + (size_t)D_ * D_;             // [DFF][D]
    __half* W2T = W1T + (size_t)D_ * DFF_;           // [D][DFF]

    cudaFuncSetAttribute(flash_attn_f16,
                         cudaFuncAttributeMaxDynamicSharedMemorySize, FA_SMEM_BYTES);
    cudaFuncSetAttribute(gemm_f16<1>, cudaFuncAttributeMaxDynamicSharedMemorySize, F_SMEM_BYTES);
    cudaFuncSetAttribute(gemm_f16<2>, cudaFuncAttributeMaxDynamicSharedMemorySize, F_SMEM_BYTES);
    cudaFuncSetAttribute(gemm_qkv,    cudaFuncAttributeMaxDynamicSharedMemorySize, F_SMEM_BYTES);

    // 0. all weight transposes -> fp16, single launch
    transpose_all<<<12288, dim3(32, 8)>>>(Wq, Wk, Wv, Wo, W1, W2,
                                          WqT, WkT, WvT, WoT, W1T, W2T);

    dim3 gD(D_ / 128, M_ / 128);        // (8, 32)
    dim3 gQKV(D_ / 128, M_ / 128, 3);   // fused QKV
    dim3 gF(DFF_ / 128, M_ / 128);      // (32, 32)

    // 1. LN1 -> fp16
    layernorm_kernel<<<M_, 256>>>(x, a1, g1, hbuf);
    // 2. QKV projections (fp16 gemm, fp16 permuted store, Q scaled 0.125*log2e)
    gemm_qkv<<<gQKV, 256, F_SMEM_BYTES>>>(hbuf, WqT, bq, bk, bv, qb, kb, vb);
    // 3. attention (fp16 tensor-core, P-in-register, base-2 softmax, 3-stage KV)
    flash_attn_f16<<<dim3(S_ / 128, B_ * H_), 256, FA_SMEM_BYTES>>>(qb, kb, vb, ctx);
    // 4. O projection + residual 1 (fp32 exact residual)
    gemm_f16<2><<<gD, 256, F_SMEM_BYTES>>>(ctx, WoT, bo, x, x2, D_, D_);
    // 5. LN2 -> fp16
    layernorm_kernel<<<M_, 256>>>(x2, a2, g2, hbuf);
    // 6. FFN up + ReLU -> fp16
    gemm_f16<1><<<gF, 256, F_SMEM_BYTES>>>(hbuf, W1T, b1, nullptr, ffb, DFF_, D_);
    // 7. FFN down + residual 2 -> output (fp32)
    gemm_f16<2><<<gD, 256, F_SMEM_BYTES>>>(ffb, W2T, b2, x2, out, D_, DFF_);
}